// round 12
// baseline (speedup 1.0000x reference)
#include <cuda_runtime.h>
#include <cuda_fp16.h>
#include <mma.h>
#include <cstdint>

using namespace nvcuda;

#define Bb 32
#define Nn 4096
#define Mm 512
#define Cc 256
#define KF 2080            // folded forward K (0..2048 data, padded to 65*32)
#define NH 2048            // half length for inverse rows

// ---------------------------------------------------------------------------
// Global scratch (static __device__ — no runtime allocation)
// ---------------------------------------------------------------------------
__device__ __align__(16) __half g_Acos[Mm * KF];
__device__ __align__(16) __half g_Asin[Mm * KF];
__device__ __align__(16) __half g_Vp[(size_t)Bb * KF * Cc];
__device__ __align__(16) __half g_Vm[(size_t)Bb * KF * Cc];
__device__ __align__(16) __half g_icos[NH * Mm];
__device__ __align__(16) __half g_isin[NH * Mm];
__device__ __align__(16) __half g_R16[(size_t)Mm * Cc * Cc];
__device__ __align__(16) __half g_Fre16[(size_t)Bb * Mm * Cc];
__device__ __align__(16) __half g_Fim16[(size_t)Bb * Mm * Cc];
__device__ __align__(16) __half g_Gre16[(size_t)Bb * Mm * Cc];
__device__ __align__(16) __half g_Gim16[(size_t)Bb * Mm * Cc];

// ---------------------------------------------------------------------------
__device__ __forceinline__ uint32_t s2u(const void* p) {
    uint32_t a;
    asm("{ .reg .u64 t; cvta.to.shared.u64 t, %1; cvt.u32.u64 %0, t; }"
        : "=r"(a) : "l"(p));
    return a;
}

#define CP16(dst, src) \
    asm volatile("cp.async.cg.shared.global [%0], [%1], 16;" :: "r"(dst), "l"(src))
#define CP_COMMIT() asm volatile("cp.async.commit_group;")
#define CP_WAIT3()  asm volatile("cp.async.wait_group 3;" ::: "memory")
#define CP_WAIT2()  asm volatile("cp.async.wait_group 2;" ::: "memory")
#define CP_WAIT1()  asm volatile("cp.async.wait_group 1;" ::: "memory")
#define CP_WAIT0()  asm volatile("cp.async.wait_group 0;" ::: "memory")

typedef wmma::fragment<wmma::matrix_a, 16, 16, 16, __half, wmma::row_major> FragA;
typedef wmma::fragment<wmma::matrix_b, 16, 16, 16, __half, wmma::row_major> FragB;
typedef wmma::fragment<wmma::accumulator, 16, 16, 16, float> FragC;

// ---------------------------------------------------------------------------
// Fused prep (one launch, permuted block order to mix DRAM- and MUFU-bound).
//   [0, 32768)      pack_R
//   [32768, 36928)  genA_fwd
//   [36928, 41024)  genA_inv
//   [41024, 57664)  packVpVm
// ---------------------------------------------------------------------------
#define PREP_BLOCKS 57664

__global__ __launch_bounds__(256) void prep_all(const float* __restrict__ v,
                                                const float* __restrict__ R) {
    const int tid = threadIdx.x;
    unsigned u = (unsigned)(((unsigned long long)blockIdx.x * 48611ull) % PREP_BLOCKS);

    if (u < 32768u) {
        size_t idx4 = (size_t)u * 256 + tid;
        size_t base = idx4 * 4;
        int m = (int)(base >> 16);
        float sc = (m == 0) ? (1.0f / Nn) : (2.0f / Nn);
        float4 x = *(const float4*)(R + base);
        *(__half2*)(g_R16 + base)     = __half2{__float2half(x.x * sc), __float2half(x.y * sc)};
        *(__half2*)(g_R16 + base + 2) = __half2{__float2half(x.z * sc), __float2half(x.w * sc)};
    } else if (u < 36928u) {
        int idx = (int)(u - 32768u) * 256 + tid;
        int m = idx / KF, k = idx - m * KF;
        int t = (int)(((long long)m * k) & (Nn - 1));
        float s, c;
        sincospif((float)t * (1.0f / 2048.0f), &s, &c);
        g_Acos[idx] = __float2half(c);
        g_Asin[idx] = __float2half(-s);
    } else if (u < 41024u) {
        int idx = (int)(u - 36928u) * 256 + tid;
        int n = idx >> 9, m = idx & 511;
        int t = (int)(((long long)m * n) & (Nn - 1));
        float s, c;
        sincospif((float)t * (1.0f / 2048.0f), &s, &c);
        g_icos[idx] = __float2half(c);
        g_isin[idx] = __float2half(s);
    } else {
        size_t idx4 = (size_t)(u - 41024u) * 256 + tid;
        int b = (int)(idx4 / (KF * 64));
        int rem = (int)(idx4 - (size_t)b * (KF * 64));
        int k = rem >> 6, i = (rem & 63) * 4;
        float4 vp, vm;
        if (k == 0) {
            vp = *(const float4*)(v + ((size_t)b * Nn) * Cc + i);
            vm = make_float4(0.f, 0.f, 0.f, 0.f);
        } else if (k < 2048) {
            float4 a = *(const float4*)(v + ((size_t)b * Nn + k) * Cc + i);
            float4 c = *(const float4*)(v + ((size_t)b * Nn + (Nn - k)) * Cc + i);
            vp = make_float4(a.x + c.x, a.y + c.y, a.z + c.z, a.w + c.w);
            vm = make_float4(a.x - c.x, a.y - c.y, a.z - c.z, a.w - c.w);
        } else if (k == 2048) {
            vp = *(const float4*)(v + ((size_t)b * Nn + 2048) * Cc + i);
            vm = make_float4(0.f, 0.f, 0.f, 0.f);
        } else {
            vp = make_float4(0.f, 0.f, 0.f, 0.f);
            vm = vp;
        }
        size_t base = ((size_t)b * KF + k) * Cc + i;
        *(__half2*)(g_Vp + base)     = __half2{__float2half(vp.x), __float2half(vp.y)};
        *(__half2*)(g_Vp + base + 2) = __half2{__float2half(vp.z), __float2half(vp.w)};
        *(__half2*)(g_Vm + base)     = __half2{__float2half(vm.x), __float2half(vm.y)};
        *(__half2*)(g_Vm + base + 2) = __half2{__float2half(vm.z), __float2half(vm.w)};
    }
}

// ---------------------------------------------------------------------------
// Forward WMMA GEMM (round-9 proven config, unchanged).
// CTA 128(m) x 256(i), 512 threads, 16 warps, warp tile 32x64.
// ---------------------------------------------------------------------------
#define STAGE 27136

__global__ __launch_bounds__(512) void fwd_gemm() {
    extern __shared__ __align__(16) char sm[];
    const uint32_t sb = s2u(sm);
    const int tid = threadIdx.x;
    const int warp = tid >> 5, lane = tid & 31;
    const int wm = warp >> 2, wn = warp & 3;
    const int b = blockIdx.z;
    const int y = blockIdx.y;
    const int comp = (y >= 4) ? 1 : 0;
    const int yt = comp ? (y - 4) : y;

    const __half* Ap = comp ? g_Asin : g_Acos;
    const __half* Bp = comp ? g_Vm : g_Vp;
    __half* Fout = comp ? g_Fim16 : g_Fre16;
    const int row0 = yt * 128;
    const int NCH = KF / 32;

    FragC acc[2][4];
    #pragma unroll
    for (int a = 0; a < 2; a++)
        #pragma unroll
        for (int j = 0; j < 4; j++) wmma::fill_fragment(acc[a][j], 0.0f);

    const int ar = tid >> 2, aq = tid & 3;
    const int br = tid >> 4, bs = tid & 15;

    auto load = [&](int stage, int k0) {
        uint32_t s0 = sb + stage * STAGE;
        size_t ga = (size_t)(row0 + ar) * KF + k0 + aq * 8;
        CP16(s0 + ar * 80 + aq * 16, Ap + ga);
        size_t gb = ((size_t)b * KF + k0 + br) * Cc + bs * 8;
        uint32_t bd = s0 + 10240 + br * 528 + bs * 16;
        CP16(bd, Bp + gb);
        CP16(bd + 256, Bp + gb + 128);
        CP_COMMIT();
    };

    load(0, 0);
    load(1, 32);
    load(2, 64);

    int stage = 0;
    for (int c = 0; c < NCH; c++) {
        if (c + 3 < NCH) {
            int ns = stage + 3; if (ns >= 4) ns -= 4;
            load(ns, (c + 3) * 32);
            CP_WAIT3();
        } else if (c + 2 < NCH) {
            CP_WAIT2();
        } else if (c + 1 < NCH) {
            CP_WAIT1();
        } else {
            CP_WAIT0();
        }
        __syncthreads();

        const char* base = sm + stage * STAGE;
        const __half* As = (const __half*)(base);
        const __half* Bs = (const __half*)(base + 10240);

        #pragma unroll
        for (int ks = 0; ks < 2; ks++) {
            const int kk = ks * 16;
            FragB bf[4];
            #pragma unroll
            for (int j = 0; j < 4; j++)
                wmma::load_matrix_sync(bf[j], Bs + kk * 264 + wn * 64 + j * 16, 264);
            #pragma unroll
            for (int ms = 0; ms < 2; ms++) {
                FragA af;
                wmma::load_matrix_sync(af, As + (wm * 32 + ms * 16) * 40 + kk, 40);
                #pragma unroll
                for (int j = 0; j < 4; j++)
                    wmma::mma_sync(acc[ms][j], af, bf[j], acc[ms][j]);
            }
        }
        __syncthreads();
        stage++; if (stage >= 4) stage = 0;
    }

    float* patch = (float*)sm + warp * 1088;
    #pragma unroll
    for (int ms = 0; ms < 2; ms++) {
        #pragma unroll
        for (int j = 0; j < 4; j++)
            wmma::store_matrix_sync(patch + j * 16, acc[ms][j], 68, wmma::mem_row_major);
        __syncwarp();
        int mrow = row0 + wm * 32 + ms * 16;
        #pragma unroll
        for (int rr = 0; rr < 16; rr++) {
            float x0 = patch[rr * 68 + lane * 2];
            float x1 = patch[rr * 68 + lane * 2 + 1];
            *(__half2*)(Fout + ((size_t)b * Mm + mrow + rr) * Cc + wn * 64 + lane * 2)
                = __half2{__float2half(x0), __float2half(x1)};
        }
        __syncwarp();
    }
}

// ---------------------------------------------------------------------------
// Mid WMMA (unchanged; 2 CTAs/SM via bounce overlap).
// ---------------------------------------------------------------------------
#define MAST 16896
#define MBOFF 33792

__global__ __launch_bounds__(256, 2) void mid_wmma() {
    extern __shared__ __align__(16) char sm[];
    const uint32_t sb = s2u(sm);
    const int tid = threadIdx.x;
    const int warp = tid >> 5, lane = tid & 31;
    const int m = blockIdx.x;

    __half* Are = (__half*)sm;
    __half* Aim = (__half*)(sm + MAST);

    #pragma unroll
    for (int it = 0; it < 8; it++) {
        int idx = tid + 256 * it;
        int plane = idx >> 10, rem = idx & 1023;
        int row = rem >> 5, seg = rem & 31;
        const __half* src = (plane ? g_Fim16 : g_Fre16)
                            + ((size_t)row * Mm + m) * Cc + seg * 8;
        uint32_t dst = sb + plane * MAST + row * 528 + seg * 16;
        CP16(dst, src);
    }
    CP_COMMIT();

    const int kr = tid >> 3, seg = tid & 7;
    auto loadB = [&](int stage, int c) {
        uint32_t s0 = sb + MBOFF + stage * MAST;
        size_t gb = ((size_t)m * Cc + c * 32 + kr) * Cc + seg * 32;
        uint32_t bd = s0 + kr * 528 + seg * 64;
        CP16(bd,      g_R16 + gb);
        CP16(bd + 16, g_R16 + gb + 8);
        CP16(bd + 32, g_R16 + gb + 16);
        CP16(bd + 48, g_R16 + gb + 24);
        CP_COMMIT();
    };

    loadB(0, 0);
    loadB(1, 1);
    loadB(2, 2);

    FragC accR[2][2], accI[2][2];
    #pragma unroll
    for (int a = 0; a < 2; a++)
        #pragma unroll
        for (int j = 0; j < 2; j++) {
            wmma::fill_fragment(accR[a][j], 0.0f);
            wmma::fill_fragment(accI[a][j], 0.0f);
        }

    int stage = 0;
    for (int c = 0; c < 8; c++) {
        if (c + 3 < 8) {
            int ns = stage + 3; if (ns >= 4) ns -= 4;
            loadB(ns, c + 3);
            CP_WAIT3();
        } else if (c + 2 < 8) {
            CP_WAIT2();
        } else if (c + 1 < 8) {
            CP_WAIT1();
        } else {
            CP_WAIT0();
        }
        __syncthreads();

        const __half* Bs = (const __half*)(sm + MBOFF + stage * MAST);
        #pragma unroll
        for (int ks = 0; ks < 2; ks++) {
            const int kk = c * 32 + ks * 16;
            FragB bf[2];
            #pragma unroll
            for (int j = 0; j < 2; j++)
                wmma::load_matrix_sync(bf[j], Bs + (ks * 16) * 264 + warp * 32 + j * 16, 264);
            #pragma unroll
            for (int ms = 0; ms < 2; ms++) {
                FragA ar_, ai_;
                wmma::load_matrix_sync(ar_, Are + ms * 16 * 264 + kk, 264);
                wmma::load_matrix_sync(ai_, Aim + ms * 16 * 264 + kk, 264);
                #pragma unroll
                for (int j = 0; j < 2; j++) {
                    wmma::mma_sync(accR[ms][j], ar_, bf[j], accR[ms][j]);
                    wmma::mma_sync(accI[ms][j], ai_, bf[j], accI[ms][j]);
                }
            }
        }
        __syncthreads();
        stage++; if (stage >= 4) stage = 0;
    }

    float* bre = (float*)sm + warp * 2560;
    float* bim = bre + 1280;
    #pragma unroll
    for (int ms = 0; ms < 2; ms++)
        #pragma unroll
        for (int j = 0; j < 2; j++) {
            wmma::store_matrix_sync(bre + ms * 16 * 40 + j * 16, accR[ms][j], 40, wmma::mem_row_major);
            wmma::store_matrix_sync(bim + ms * 16 * 40 + j * 16, accI[ms][j], 40, wmma::mem_row_major);
        }
    __syncwarp();
    #pragma unroll 4
    for (int r = 0; r < 32; r++) {
        size_t g = ((size_t)r * Mm + m) * Cc + warp * 32 + lane;
        g_Gre16[g] = __float2half(bre[r * 40 + lane]);
        g_Gim16[g] = __float2half(bim[r * 40 + lane]);
    }
}

// ---------------------------------------------------------------------------
// Inverse WMMA GEMM with fused combine — 2 CTAs/SM version.
// CTA 128(n) x 64(o), 256 threads, 8 warps.
// Warps 0-3: C = cos@Gre (warp tile 32x64). Warps 4-7: S = sin@Gim.
// Epilogue: out[n] = v[n] + C - S;  out[N-n] = v[N-n] + C + S.
// Stage (29696B): Acos[128][40] @0, Asin @10240, BGre[32][72] @20480 (4608),
//                 BGim @25088. 3 stages = 89088.
// Epilogue Cbuf/Sbuf (128x68 fp32 each = 69632) overlap stage region @0.
// grid: (4, 16, 32) = 2048 CTAs, occupancy 2/SM.
// ---------------------------------------------------------------------------
#define I2STAGE 29696

__global__ __launch_bounds__(256, 2) void inv_gemm(const float* __restrict__ v,
                                                   float* __restrict__ out) {
    extern __shared__ __align__(16) char sm[];
    const uint32_t sb = s2u(sm);
    const int tid = threadIdx.x;
    const int warp = tid >> 5;
    const int comp = warp >> 2;          // 0: C (cos,Gre)   1: S (sin,Gim)
    const int wm = warp & 3;             // 4 row-blocks of 32
    const int colt = blockIdx.x, yt = blockIdx.y, b = blockIdx.z;
    const int row0 = yt * 128, c0 = colt * 64;
    const int NCH = Mm / 32;             // 16

    FragC acc[2][4];
    #pragma unroll
    for (int a = 0; a < 2; a++)
        #pragma unroll
        for (int j = 0; j < 4; j++) wmma::fill_fragment(acc[a][j], 0.0f);

    const int ar = tid >> 1, aq = tid & 1;   // A: 128 rows x 2 halves(32B), both planes
    const int br = tid >> 3, bs = tid & 7;   // B: 32 rows x 8 segs(16B), both planes

    auto load = [&](int stage, int k0) {
        uint32_t s0 = sb + stage * I2STAGE;
        size_t ga = (size_t)(row0 + ar) * Mm + k0 + aq * 16;
        uint32_t ad = s0 + ar * 80 + aq * 32;
        CP16(ad,         g_icos + ga);
        CP16(ad + 16,    g_icos + ga + 8);
        CP16(ad + 10240, g_isin + ga);
        CP16(ad + 10256, g_isin + ga + 8);
        size_t gb = ((size_t)b * Mm + k0 + br) * Cc + c0 + bs * 8;
        uint32_t bd = s0 + 20480 + br * 144 + bs * 16;
        CP16(bd,        g_Gre16 + gb);
        CP16(bd + 4608, g_Gim16 + gb);
        CP_COMMIT();
    };

    load(0, 0);
    load(1, 32);

    int stage = 0;
    for (int c = 0; c < NCH; c++) {
        if (c + 2 < NCH) {
            int ns = stage + 2; if (ns >= 3) ns -= 3;
            load(ns, (c + 2) * 32);
            CP_WAIT2();
        } else if (c + 1 < NCH) {
            CP_WAIT1();
        } else {
            CP_WAIT0();
        }
        __syncthreads();

        const char* base = sm + stage * I2STAGE;
        const __half* As = (const __half*)(base + comp * 10240);
        const __half* Bs = (const __half*)(base + 20480 + comp * 4608);

        #pragma unroll
        for (int ks = 0; ks < 2; ks++) {
            const int kk = ks * 16;
            FragB bf[4];
            #pragma unroll
            for (int j = 0; j < 4; j++)
                wmma::load_matrix_sync(bf[j], Bs + kk * 72 + j * 16, 72);
            #pragma unroll
            for (int ms = 0; ms < 2; ms++) {
                FragA af;
                wmma::load_matrix_sync(af, As + (wm * 32 + ms * 16) * 40 + kk, 40);
                #pragma unroll
                for (int j = 0; j < 4; j++)
                    wmma::mma_sync(acc[ms][j], af, bf[j], acc[ms][j]);
            }
        }
        __syncthreads();
        stage++; if (stage >= 3) stage = 0;
    }

    // Epilogue: C and S to smem (overlapping dead stage region), fused combine.
    float* Cbuf = (float*)sm;                 // 128 x 68 fp32 = 34816B
    float* Sbuf = Cbuf + 128 * 68;            // +34816B (total 69632 < 89088)
    float* buf = comp ? Sbuf : Cbuf;
    #pragma unroll
    for (int ms = 0; ms < 2; ms++)
        #pragma unroll
        for (int j = 0; j < 4; j++)
            wmma::store_matrix_sync(buf + (wm * 32 + ms * 16) * 68 + j * 16,
                                    acc[ms][j], 68, wmma::mem_row_major);
    __syncthreads();

    #pragma unroll
    for (int it = 0; it < 8; it++) {
        int idx = tid + 256 * it;            // 0..2047 (128 rows x 16 float4)
        int r = idx >> 4, c4 = idx & 15;
        float4 C = *(const float4*)(Cbuf + r * 68 + c4 * 4);
        float4 S = *(const float4*)(Sbuf + r * 68 + c4 * 4);
        int n = row0 + r;
        int o = c0 + c4 * 4;
        size_t i1 = ((size_t)b * Nn + n) * Cc + o;
        float4 v1 = *(const float4*)(v + i1);
        *(float4*)(out + i1) = make_float4(v1.x + C.x - S.x, v1.y + C.y - S.y,
                                           v1.z + C.z - S.z, v1.w + C.w - S.w);
        if (n > 0) {
            size_t i2 = ((size_t)b * Nn + (Nn - n)) * Cc + o;
            float4 v2 = *(const float4*)(v + i2);
            *(float4*)(out + i2) = make_float4(v2.x + C.x + S.x, v2.y + C.y + S.y,
                                               v2.z + C.z + S.z, v2.w + C.w + S.w);
        }
    }
}

// out[b,2048,o] = v[b,2048,o] + sum_m (-1)^m * Gre'[b,m,o]   (reads fp16 Gre)
__global__ __launch_bounds__(64) void row2048(const float* __restrict__ v,
                                              float* __restrict__ out) {
    const int b = blockIdx.x;
    const int o = threadIdx.x * 4;
    float acc0 = 0.f, acc1 = 0.f, acc2 = 0.f, acc3 = 0.f;
    #pragma unroll 8
    for (int m = 0; m < Mm; m++) {
        float sgn = (m & 1) ? -1.0f : 1.0f;
        const __half* g = g_Gre16 + ((size_t)b * Mm + m) * Cc + o;
        __half2 a = *(const __half2*)(g);
        __half2 bb = *(const __half2*)(g + 2);
        acc0 += sgn * __half2float(a.x);
        acc1 += sgn * __half2float(a.y);
        acc2 += sgn * __half2float(bb.x);
        acc3 += sgn * __half2float(bb.y);
    }
    size_t idx = ((size_t)b * Nn + 2048) * Cc + o;
    float4 vv = *(const float4*)(v + idx);
    *(float4*)(out + idx) = make_float4(vv.x + acc0, vv.y + acc1,
                                        vv.z + acc2, vv.w + acc3);
}

// ---------------------------------------------------------------------------
extern "C" void kernel_launch(void* const* d_in, const int* in_sizes, int n_in,
                              void* d_out, int out_size) {
    const float* v = (const float*)d_in[0];
    const float* R = (const float*)d_in[1];
    float* out = (float*)d_out;

    const int smF = 4 * STAGE;           // 108544
    const int smMid = MBOFF + 4 * MAST;  // 101376
    const int smInv = 3 * I2STAGE;       // 89088
    cudaFuncSetAttribute(fwd_gemm, cudaFuncAttributeMaxDynamicSharedMemorySize, smF);
    cudaFuncSetAttribute(mid_wmma, cudaFuncAttributeMaxDynamicSharedMemorySize, smMid);
    cudaFuncSetAttribute(inv_gemm, cudaFuncAttributeMaxDynamicSharedMemorySize, smInv);

    prep_all<<<PREP_BLOCKS, 256>>>(v, R);
    fwd_gemm<<<dim3(1, 8, Bb), 512, smF>>>();
    mid_wmma<<<Mm, 256, smMid>>>();
    inv_gemm<<<dim3(4, 16, Bb), 256, smInv>>>(v, out);
    row2048<<<Bb, 64>>>(v, out);
}

// round 13
// speedup vs baseline: 1.2846x; 1.2846x over previous
#include <cuda_runtime.h>
#include <cuda_fp16.h>
#include <mma.h>
#include <cstdint>

using namespace nvcuda;

#define Bb 32
#define Nn 4096
#define Mm 512
#define Cc 256
#define KF2 1056           // double-folded forward K (0..1024 data, pad to 33*32)

// ---------------------------------------------------------------------------
// Global scratch (static __device__ — no runtime allocation)
// ---------------------------------------------------------------------------
// Forward twiddles: 4 planes [256 m'][KF2]: cos_e, cos_o, -sin_e, -sin_o
__device__ __align__(16) __half g_Af[(size_t)4 * 256 * KF2];
// Double-folded v: 4 planes per batch [b][4][KF2][256]: vpp, vpm, vmm, vmp
__device__ __align__(16) __half g_V4[(size_t)Bb * 4 * KF2 * Cc];
// Inverse twiddles: 4 planes [1024 n][256 m']: cos_e, cos_o, sin_e, sin_o
__device__ __align__(16) __half g_Ai[(size_t)4 * 1024 * 256];
// Scaled R fp16 (w_m/N folded): [512 m][256 i][256 o]
__device__ __align__(16) __half g_R16[(size_t)Mm * Cc * Cc];
// Forward spectra fp16: [b][512][256]
__device__ __align__(16) __half g_Fre16[(size_t)Bb * Mm * Cc];
__device__ __align__(16) __half g_Fim16[(size_t)Bb * Mm * Cc];
// Transformed spectra, parity-split: [b][4][256][256]: GreE, GreO, GimE, GimO
__device__ __align__(16) __half g_G4[(size_t)Bb * 4 * 256 * 256];

// ---------------------------------------------------------------------------
__device__ __forceinline__ uint32_t s2u(const void* p) {
    uint32_t a;
    asm("{ .reg .u64 t; cvta.to.shared.u64 t, %1; cvt.u32.u64 %0, t; }"
        : "=r"(a) : "l"(p));
    return a;
}

#define CP16(dst, src) \
    asm volatile("cp.async.cg.shared.global [%0], [%1], 16;" :: "r"(dst), "l"(src))
#define CP_COMMIT() asm volatile("cp.async.commit_group;")
#define CP_WAIT3()  asm volatile("cp.async.wait_group 3;" ::: "memory")
#define CP_WAIT2()  asm volatile("cp.async.wait_group 2;" ::: "memory")
#define CP_WAIT1()  asm volatile("cp.async.wait_group 1;" ::: "memory")
#define CP_WAIT0()  asm volatile("cp.async.wait_group 0;" ::: "memory")

typedef wmma::fragment<wmma::matrix_a, 16, 16, 16, __half, wmma::row_major> FragA;
typedef wmma::fragment<wmma::matrix_b, 16, 16, 16, __half, wmma::row_major> FragB;
typedef wmma::fragment<wmma::accumulator, 16, 16, 16, float> FragC;

// ---------------------------------------------------------------------------
// Fused prep (one launch, permuted block order).
//   [0, 32768)      pack_R       (512*256*256/4/256)
//   [32768, 36992)  genA_fwd     (4*256*1056/256 = 4224)
//   [36992, 41088)  genA_inv     (4*1024*256/256 = 4096)
//   [41088, 49536)  packV4       (32*1056*64/256 = 8448)
// ---------------------------------------------------------------------------
#define PREP_BLOCKS 49536

__global__ __launch_bounds__(256) void prep_all(const float* __restrict__ v,
                                                const float* __restrict__ R) {
    const int tid = threadIdx.x;
    unsigned u = (unsigned)(((unsigned long long)blockIdx.x * 48611ull) % PREP_BLOCKS);

    if (u < 32768u) {
        // ---- pack_R: R fp32 -> fp16, w_m/N folded ----
        size_t idx4 = (size_t)u * 256 + tid;
        size_t base = idx4 * 4;
        int m = (int)(base >> 16);
        float sc = (m == 0) ? (1.0f / Nn) : (2.0f / Nn);
        float4 x = *(const float4*)(R + base);
        *(__half2*)(g_R16 + base)     = __half2{__float2half(x.x * sc), __float2half(x.y * sc)};
        *(__half2*)(g_R16 + base + 2) = __half2{__float2half(x.z * sc), __float2half(x.w * sc)};
    } else if (u < 36992u) {
        // ---- genA_fwd: [comp][m'][k]; comp: 0 cos_e, 1 cos_o, 2 -sin_e, 3 -sin_o
        int idx = (int)(u - 32768u) * 256 + tid;
        int comp = idx / (256 * KF2);
        int rem = idx - comp * (256 * KF2);
        int mp = rem / KF2, k = rem - mp * KF2;
        int m = 2 * mp + (comp & 1);
        float val = 0.0f;
        if (k <= 1024) {
            int t = (int)(((long long)m * k) & (Nn - 1));
            float s, c;
            sincospif((float)t * (1.0f / 2048.0f), &s, &c);
            val = (comp < 2) ? c : -s;
        }
        g_Af[idx] = __float2half(val);
    } else if (u < 41088u) {
        // ---- genA_inv: [comp][n][m']; comp: 0 cos_e, 1 cos_o, 2 sin_e, 3 sin_o
        int idx = (int)(u - 36992u) * 256 + tid;
        int comp = idx >> 18;
        int rem = idx & 262143;
        int n = rem >> 8, mp = rem & 255;
        int m = 2 * mp + (comp & 1);
        int t = (int)(((long long)m * n) & (Nn - 1));
        float s, c;
        sincospif((float)t * (1.0f / 2048.0f), &s, &c);
        g_Ai[idx] = __float2half((comp < 2) ? c : s);
    } else {
        // ---- packV4: vpp, vpm, vmm, vmp (double fold) ----
        size_t idx4 = (size_t)(u - 41088u) * 256 + tid;
        int b = (int)(idx4 / (KF2 * 64));
        int rem = (int)(idx4 - (size_t)b * (KF2 * 64));
        int k = rem >> 6, i = (rem & 63) * 4;
        float4 pp, pm, mm_, mp;
        const float* vb = v + (size_t)b * Nn * Cc;
        if (k == 0) {
            float4 a = *(const float4*)(vb + i);                       // v[0]
            float4 d = *(const float4*)(vb + (size_t)2048 * Cc + i);   // v[2048]
            pp = make_float4(a.x + d.x, a.y + d.y, a.z + d.z, a.w + d.w);
            pm = make_float4(a.x - d.x, a.y - d.y, a.z - d.z, a.w - d.w);
            mm_ = make_float4(0.f, 0.f, 0.f, 0.f);
            mp = mm_;
        } else if (k < 1024) {
            float4 a = *(const float4*)(vb + (size_t)k * Cc + i);
            float4 bq = *(const float4*)(vb + (size_t)(Nn - k) * Cc + i);
            float4 c = *(const float4*)(vb + (size_t)(2048 - k) * Cc + i);
            float4 d = *(const float4*)(vb + (size_t)(2048 + k) * Cc + i);
            pp = make_float4(a.x + bq.x + c.x + d.x, a.y + bq.y + c.y + d.y,
                             a.z + bq.z + c.z + d.z, a.w + bq.w + c.w + d.w);
            pm = make_float4(a.x + bq.x - c.x - d.x, a.y + bq.y - c.y - d.y,
                             a.z + bq.z - c.z - d.z, a.w + bq.w - c.w - d.w);
            mm_ = make_float4(a.x - bq.x - c.x + d.x, a.y - bq.y - c.y + d.y,
                              a.z - bq.z - c.z + d.z, a.w - bq.w - c.w + d.w);
            mp = make_float4(a.x - bq.x + c.x - d.x, a.y - bq.y + c.y - d.y,
                             a.z - bq.z + c.z - d.z, a.w - bq.w + c.w - d.w);
        } else if (k == 1024) {
            float4 a = *(const float4*)(vb + (size_t)1024 * Cc + i);
            float4 d = *(const float4*)(vb + (size_t)3072 * Cc + i);
            pp = make_float4(a.x + d.x, a.y + d.y, a.z + d.z, a.w + d.w);
            mp = make_float4(a.x - d.x, a.y - d.y, a.z - d.z, a.w - d.w);
            pm = make_float4(0.f, 0.f, 0.f, 0.f);
            mm_ = pm;
        } else {
            pp = make_float4(0.f, 0.f, 0.f, 0.f);
            pm = pp; mm_ = pp; mp = pp;
        }
        size_t pbase = ((size_t)b * 4) * (KF2 * (size_t)Cc) + (size_t)k * Cc + i;
        const size_t PS = (size_t)KF2 * Cc;
        *(__half2*)(g_V4 + pbase)              = __half2{__float2half(pp.x), __float2half(pp.y)};
        *(__half2*)(g_V4 + pbase + 2)          = __half2{__float2half(pp.z), __float2half(pp.w)};
        *(__half2*)(g_V4 + pbase + PS)         = __half2{__float2half(pm.x), __float2half(pm.y)};
        *(__half2*)(g_V4 + pbase + PS + 2)     = __half2{__float2half(pm.z), __float2half(pm.w)};
        *(__half2*)(g_V4 + pbase + 2 * PS)     = __half2{__float2half(mm_.x), __float2half(mm_.y)};
        *(__half2*)(g_V4 + pbase + 2 * PS + 2) = __half2{__float2half(mm_.z), __float2half(mm_.w)};
        *(__half2*)(g_V4 + pbase + 3 * PS)     = __half2{__float2half(mp.x), __float2half(mp.y)};
        *(__half2*)(g_V4 + pbase + 3 * PS + 2) = __half2{__float2half(mp.z), __float2half(mp.w)};
    }
}

// ---------------------------------------------------------------------------
// Forward WMMA GEMM (double-folded). CTA 128(m') x 256(i), 512 threads,
// 16 warps, warp tile 32x64, 4-stage cp.async, K=1056 (33 chunks).
// grid: (1, 8, 32): y = comp*2 + yt; comp: 0 re_e, 1 re_o, 2 im_e, 3 im_o.
// Stage (27136B): A[128][40] @0, B[32][264] @10240.
// Epilogue: fp16 F rows at m = 2*m' + parity.
// ---------------------------------------------------------------------------
#define STAGE 27136

__global__ __launch_bounds__(512) void fwd_gemm() {
    extern __shared__ __align__(16) char sm[];
    const uint32_t sb = s2u(sm);
    const int tid = threadIdx.x;
    const int warp = tid >> 5, lane = tid & 31;
    const int wm = warp >> 2, wn = warp & 3;
    const int b = blockIdx.z;
    const int y = blockIdx.y;
    const int comp = y >> 1, yt = y & 1;
    const int par = comp & 1;

    const __half* Ap = g_Af + (size_t)comp * 256 * KF2;
    const __half* Bp = g_V4 + ((size_t)b * 4 + comp) * ((size_t)KF2 * Cc);
    __half* Fout = (comp < 2) ? g_Fre16 : g_Fim16;
    const int row0 = yt * 128;          // in m' space
    const int NCH = KF2 / 32;           // 33

    FragC acc[2][4];
    #pragma unroll
    for (int a = 0; a < 2; a++)
        #pragma unroll
        for (int j = 0; j < 4; j++) wmma::fill_fragment(acc[a][j], 0.0f);

    const int ar = tid >> 2, aq = tid & 3;
    const int br = tid >> 4, bs = tid & 15;

    auto load = [&](int stage, int k0) {
        uint32_t s0 = sb + stage * STAGE;
        size_t ga = (size_t)(row0 + ar) * KF2 + k0 + aq * 8;
        CP16(s0 + ar * 80 + aq * 16, Ap + ga);
        size_t gb = (size_t)(k0 + br) * Cc + bs * 8;
        uint32_t bd = s0 + 10240 + br * 528 + bs * 16;
        CP16(bd, Bp + gb);
        CP16(bd + 256, Bp + gb + 128);
        CP_COMMIT();
    };

    load(0, 0);
    load(1, 32);
    load(2, 64);

    int stage = 0;
    for (int c = 0; c < NCH; c++) {
        if (c + 3 < NCH) {
            int ns = stage + 3; if (ns >= 4) ns -= 4;
            load(ns, (c + 3) * 32);
            CP_WAIT3();
        } else if (c + 2 < NCH) {
            CP_WAIT2();
        } else if (c + 1 < NCH) {
            CP_WAIT1();
        } else {
            CP_WAIT0();
        }
        __syncthreads();

        const char* base = sm + stage * STAGE;
        const __half* As = (const __half*)(base);
        const __half* Bs = (const __half*)(base + 10240);

        #pragma unroll
        for (int ks = 0; ks < 2; ks++) {
            const int kk = ks * 16;
            FragB bf[4];
            #pragma unroll
            for (int j = 0; j < 4; j++)
                wmma::load_matrix_sync(bf[j], Bs + kk * 264 + wn * 64 + j * 16, 264);
            #pragma unroll
            for (int ms = 0; ms < 2; ms++) {
                FragA af;
                wmma::load_matrix_sync(af, As + (wm * 32 + ms * 16) * 40 + kk, 40);
                #pragma unroll
                for (int j = 0; j < 4; j++)
                    wmma::mma_sync(acc[ms][j], af, bf[j], acc[ms][j]);
            }
        }
        __syncthreads();
        stage++; if (stage >= 4) stage = 0;
    }

    // Epilogue: per-warp smem patch, convert fp16, store at m = 2*m' + par.
    float* patch = (float*)sm + warp * 1088;
    #pragma unroll
    for (int ms = 0; ms < 2; ms++) {
        #pragma unroll
        for (int j = 0; j < 4; j++)
            wmma::store_matrix_sync(patch + j * 16, acc[ms][j], 68, wmma::mem_row_major);
        __syncwarp();
        int mpbase = row0 + wm * 32 + ms * 16;
        #pragma unroll
        for (int rr = 0; rr < 16; rr++) {
            float x0 = patch[rr * 68 + lane * 2];
            float x1 = patch[rr * 68 + lane * 2 + 1];
            int m = 2 * (mpbase + rr) + par;
            *(__half2*)(Fout + ((size_t)b * Mm + m) * Cc + wn * 64 + lane * 2)
                = __half2{__float2half(x0), __float2half(x1)};
        }
        __syncwarp();
    }
}

// ---------------------------------------------------------------------------
// Mid WMMA: per mode m, G[32b, 256o] = F[32b, 256i] @ R16[m] (re & im).
// 256 threads, 8 warps, warp tile 32x32, 4-stage B pipeline.
// Epilogue writes parity-split planes g_G4.
// ---------------------------------------------------------------------------
#define MAST 16896
#define MBOFF 33792

__global__ __launch_bounds__(256, 2) void mid_wmma() {
    extern __shared__ __align__(16) char sm[];
    const uint32_t sb = s2u(sm);
    const int tid = threadIdx.x;
    const int warp = tid >> 5, lane = tid & 31;
    const int m = blockIdx.x;

    __half* Are = (__half*)sm;
    __half* Aim = (__half*)(sm + MAST);

    #pragma unroll
    for (int it = 0; it < 8; it++) {
        int idx = tid + 256 * it;
        int plane = idx >> 10, rem = idx & 1023;
        int row = rem >> 5, seg = rem & 31;
        const __half* src = (plane ? g_Fim16 : g_Fre16)
                            + ((size_t)row * Mm + m) * Cc + seg * 8;
        uint32_t dst = sb + plane * MAST + row * 528 + seg * 16;
        CP16(dst, src);
    }
    CP_COMMIT();

    const int kr = tid >> 3, seg = tid & 7;
    auto loadB = [&](int stage, int c) {
        uint32_t s0 = sb + MBOFF + stage * MAST;
        size_t gb = ((size_t)m * Cc + c * 32 + kr) * Cc + seg * 32;
        uint32_t bd = s0 + kr * 528 + seg * 64;
        CP16(bd,      g_R16 + gb);
        CP16(bd + 16, g_R16 + gb + 8);
        CP16(bd + 32, g_R16 + gb + 16);
        CP16(bd + 48, g_R16 + gb + 24);
        CP_COMMIT();
    };

    loadB(0, 0);
    loadB(1, 1);
    loadB(2, 2);

    FragC accR[2][2], accI[2][2];
    #pragma unroll
    for (int a = 0; a < 2; a++)
        #pragma unroll
        for (int j = 0; j < 2; j++) {
            wmma::fill_fragment(accR[a][j], 0.0f);
            wmma::fill_fragment(accI[a][j], 0.0f);
        }

    int stage = 0;
    for (int c = 0; c < 8; c++) {
        if (c + 3 < 8) {
            int ns = stage + 3; if (ns >= 4) ns -= 4;
            loadB(ns, c + 3);
            CP_WAIT3();
        } else if (c + 2 < 8) {
            CP_WAIT2();
        } else if (c + 1 < 8) {
            CP_WAIT1();
        } else {
            CP_WAIT0();
        }
        __syncthreads();

        const __half* Bs = (const __half*)(sm + MBOFF + stage * MAST);
        #pragma unroll
        for (int ks = 0; ks < 2; ks++) {
            const int kk = c * 32 + ks * 16;
            FragB bf[2];
            #pragma unroll
            for (int j = 0; j < 2; j++)
                wmma::load_matrix_sync(bf[j], Bs + (ks * 16) * 264 + warp * 32 + j * 16, 264);
            #pragma unroll
            for (int ms = 0; ms < 2; ms++) {
                FragA ar_, ai_;
                wmma::load_matrix_sync(ar_, Are + ms * 16 * 264 + kk, 264);
                wmma::load_matrix_sync(ai_, Aim + ms * 16 * 264 + kk, 264);
                #pragma unroll
                for (int j = 0; j < 2; j++) {
                    wmma::mma_sync(accR[ms][j], ar_, bf[j], accR[ms][j]);
                    wmma::mma_sync(accI[ms][j], ai_, bf[j], accI[ms][j]);
                }
            }
        }
        __syncthreads();
        stage++; if (stage >= 4) stage = 0;
    }

    float* bre = (float*)sm + warp * 2560;
    float* bim = bre + 1280;
    #pragma unroll
    for (int ms = 0; ms < 2; ms++)
        #pragma unroll
        for (int j = 0; j < 2; j++) {
            wmma::store_matrix_sync(bre + ms * 16 * 40 + j * 16, accR[ms][j], 40, wmma::mem_row_major);
            wmma::store_matrix_sync(bim + ms * 16 * 40 + j * 16, accI[ms][j], 40, wmma::mem_row_major);
        }
    __syncwarp();
    const int preP = m & 1;           // Gre plane 0/1
    const int pimP = 2 + (m & 1);     // Gim plane 2/3
    const int mrow = m >> 1;
    #pragma unroll 4
    for (int r = 0; r < 32; r++) {
        size_t gre = (((size_t)r * 4 + preP) * 256 + mrow) * Cc + warp * 32 + lane;
        size_t gim = (((size_t)r * 4 + pimP) * 256 + mrow) * Cc + warp * 32 + lane;
        g_G4[gre] = __float2half(bre[r * 40 + lane]);
        g_G4[gim] = __float2half(bim[r * 40 + lane]);
    }
}

// ---------------------------------------------------------------------------
// Inverse WMMA GEMM (double-folded) with fused combine.
// CTA 64(n) x 128(o), 512 threads, 16 warps.
// comp = warp>>2: 0 Ce(cos_e@GreE), 1 Co(cos_o@GreO), 2 Se(sin_e@GimE), 3 So.
// Warp tile 32x64 (w4 = warp&3: wm = w4>>1 rows, wn = w4&1 cols). K=256.
// Epilogue (n in [0,1024)):
//   out[n]      = v + (Ce+Co) - (Se+So)
//   out[4096-n] = v + (Ce+Co) + (Se+So)      (n>0)
//   out[2048-n] = v + (Ce-Co) + (Se-So)
//   out[2048+n] = v + (Ce-Co) - (Se-So)      (n>0)
// Stage (55296B): A 4x[64][40] @0 (20480), B 4x[32][136] @20480 (34816).
// 3 stages = 165888; epilogue 4x(64x132 fp32) = 135168 overlaps.
// grid: (2, 16, 32)
// ---------------------------------------------------------------------------
#define I3STAGE 55296

__global__ __launch_bounds__(512) void inv_gemm(const float* __restrict__ v,
                                                float* __restrict__ out) {
    extern __shared__ __align__(16) char sm[];
    const uint32_t sb = s2u(sm);
    const int tid = threadIdx.x;
    const int warp = tid >> 5;
    const int comp = warp >> 2;
    const int w4 = warp & 3;
    const int wm = w4 >> 1, wn = w4 & 1;
    const int colt = blockIdx.x, yt = blockIdx.y, b = blockIdx.z;
    const int row0 = yt * 64, c0 = colt * 128;
    const int NCH = 8;                   // K = 256

    FragC acc[2][4];
    #pragma unroll
    for (int a = 0; a < 2; a++)
        #pragma unroll
        for (int j = 0; j < 4; j++) wmma::fill_fragment(acc[a][j], 0.0f);

    // A loader: plane = tid>>7, row = (tid&127)>>1, seg = tid&1 (32B)
    const int ap = tid >> 7;
    const int arow = (tid & 127) >> 1;
    const int aseg = tid & 1;
    // B loader: plane = tid>>7, row = (tid&127)>>2, seg = (tid&3) (64B)
    const int bp = tid >> 7;
    const int brow = (tid & 127) >> 2;
    const int bseg = tid & 3;

    auto load = [&](int stage, int k0) {
        uint32_t s0 = sb + stage * I3STAGE;
        size_t ga = ((size_t)ap << 18) + (size_t)(row0 + arow) * 256 + k0 + aseg * 16;
        uint32_t ad = s0 + ap * 5120 + arow * 80 + aseg * 32;
        CP16(ad,      g_Ai + ga);
        CP16(ad + 16, g_Ai + ga + 8);
        size_t gb = (((size_t)b * 4 + bp) * 256 + k0 + brow) * Cc + c0 + bseg * 32;
        uint32_t bd = s0 + 20480 + bp * 8704 + brow * 272 + bseg * 64;
        CP16(bd,      g_G4 + gb);
        CP16(bd + 16, g_G4 + gb + 8);
        CP16(bd + 32, g_G4 + gb + 16);
        CP16(bd + 48, g_G4 + gb + 24);
        CP_COMMIT();
    };

    load(0, 0);
    load(1, 32);

    int stage = 0;
    for (int c = 0; c < NCH; c++) {
        if (c + 2 < NCH) {
            int ns = stage + 2; if (ns >= 3) ns -= 3;
            load(ns, (c + 2) * 32);
            CP_WAIT2();
        } else if (c + 1 < NCH) {
            CP_WAIT1();
        } else {
            CP_WAIT0();
        }
        __syncthreads();

        const char* base = sm + stage * I3STAGE;
        const __half* As = (const __half*)(base + comp * 5120);
        const __half* Bs = (const __half*)(base + 20480 + comp * 8704);

        #pragma unroll
        for (int ks = 0; ks < 2; ks++) {
            const int kk = ks * 16;
            FragB bf[4];
            #pragma unroll
            for (int j = 0; j < 4; j++)
                wmma::load_matrix_sync(bf[j], Bs + kk * 136 + wn * 64 + j * 16, 136);
            #pragma unroll
            for (int ms = 0; ms < 2; ms++) {
                FragA af;
                wmma::load_matrix_sync(af, As + (wm * 32 + ms * 16) * 40 + kk, 40);
                #pragma unroll
                for (int j = 0; j < 4; j++)
                    wmma::mma_sync(acc[ms][j], af, bf[j], acc[ms][j]);
            }
        }
        __syncthreads();
        stage++; if (stage >= 3) stage = 0;
    }

    // Epilogue: 4 component buffers 64x132 fp32 each, overlapping stage region.
    float* bufs = (float*)sm;
    float* buf = bufs + comp * 8448;     // 64*132
    #pragma unroll
    for (int ms = 0; ms < 2; ms++)
        #pragma unroll
        for (int j = 0; j < 4; j++)
            wmma::store_matrix_sync(buf + (wm * 32 + ms * 16) * 132 + wn * 64 + j * 16,
                                    acc[ms][j], 132, wmma::mem_row_major);
    __syncthreads();

    const float* Ceb = bufs;
    const float* Cob = bufs + 8448;
    const float* Seb = bufs + 16896;
    const float* Sob = bufs + 25344;
    #pragma unroll
    for (int it = 0; it < 4; it++) {
        int idx = tid + 512 * it;          // 0..2047: 64 rows x 32 float4
        int r = idx >> 5, c4 = idx & 31;
        int off = r * 132 + c4 * 4;
        float4 Ce = *(const float4*)(Ceb + off);
        float4 Co = *(const float4*)(Cob + off);
        float4 Se = *(const float4*)(Seb + off);
        float4 So = *(const float4*)(Sob + off);
        float4 A1 = make_float4(Ce.x + Co.x, Ce.y + Co.y, Ce.z + Co.z, Ce.w + Co.w);
        float4 A2 = make_float4(Se.x + So.x, Se.y + So.y, Se.z + So.z, Se.w + So.w);
        float4 A3 = make_float4(Ce.x - Co.x, Ce.y - Co.y, Ce.z - Co.z, Ce.w - Co.w);
        float4 A4 = make_float4(Se.x - So.x, Se.y - So.y, Se.z - So.z, Se.w - So.w);
        int n = row0 + r;
        int o = c0 + c4 * 4;
        size_t rowb = (size_t)b * Nn;
        {
            size_t i1 = (rowb + n) * Cc + o;
            float4 vv = *(const float4*)(v + i1);
            *(float4*)(out + i1) = make_float4(vv.x + A1.x - A2.x, vv.y + A1.y - A2.y,
                                               vv.z + A1.z - A2.z, vv.w + A1.w - A2.w);
        }
        if (n > 0) {
            size_t i2 = (rowb + (Nn - n)) * Cc + o;
            float4 vv = *(const float4*)(v + i2);
            *(float4*)(out + i2) = make_float4(vv.x + A1.x + A2.x, vv.y + A1.y + A2.y,
                                               vv.z + A1.z + A2.z, vv.w + A1.w + A2.w);
        }
        {
            size_t i3 = (rowb + (2048 - n)) * Cc + o;
            float4 vv = *(const float4*)(v + i3);
            *(float4*)(out + i3) = make_float4(vv.x + A3.x + A4.x, vv.y + A3.y + A4.y,
                                               vv.z + A3.z + A4.z, vv.w + A3.w + A4.w);
        }
        if (n > 0) {
            size_t i4 = (rowb + (2048 + n)) * Cc + o;
            float4 vv = *(const float4*)(v + i4);
            *(float4*)(out + i4) = make_float4(vv.x + A3.x - A4.x, vv.y + A3.y - A4.y,
                                               vv.z + A3.z - A4.z, vv.w + A3.w - A4.w);
        }
    }
}

// ---------------------------------------------------------------------------
// rowQ: n = 1024 case. C = sum_{m'} (-1)^{m'} GreE[m'], S = sum (-1)^{m'} GimO.
// out[1024] = v + C - S;  out[3072] = v + C + S.   grid (32), 64 threads.
// ---------------------------------------------------------------------------
__global__ __launch_bounds__(64) void rowQ(const float* __restrict__ v,
                                           float* __restrict__ out) {
    const int b = blockIdx.x;
    const int o = threadIdx.x * 4;
    float c0 = 0.f, c1 = 0.f, c2 = 0.f, c3 = 0.f;
    float s0 = 0.f, s1 = 0.f, s2 = 0.f, s3 = 0.f;
    const __half* GreE = g_G4 + ((size_t)b * 4 + 0) * 65536;
    const __half* GimO = g_G4 + ((size_t)b * 4 + 3) * 65536;
    #pragma unroll 8
    for (int mp = 0; mp < 256; mp++) {
        float sgn = (mp & 1) ? -1.0f : 1.0f;
        const __half* gr = GreE + (size_t)mp * Cc + o;
        const __half* gi = GimO + (size_t)mp * Cc + o;
        __half2 ra = *(const __half2*)(gr), rb = *(const __half2*)(gr + 2);
        __half2 ia = *(const __half2*)(gi), ib = *(const __half2*)(gi + 2);
        c0 += sgn * __half2float(ra.x); c1 += sgn * __half2float(ra.y);
        c2 += sgn * __half2float(rb.x); c3 += sgn * __half2float(rb.y);
        s0 += sgn * __half2float(ia.x); s1 += sgn * __half2float(ia.y);
        s2 += sgn * __half2float(ib.x); s3 += sgn * __half2float(ib.y);
    }
    size_t i1 = ((size_t)b * Nn + 1024) * Cc + o;
    size_t i2 = ((size_t)b * Nn + 3072) * Cc + o;
    float4 v1 = *(const float4*)(v + i1);
    float4 v2 = *(const float4*)(v + i2);
    *(float4*)(out + i1) = make_float4(v1.x + c0 - s0, v1.y + c1 - s1,
                                       v1.z + c2 - s2, v1.w + c3 - s3);
    *(float4*)(out + i2) = make_float4(v2.x + c0 + s0, v2.y + c1 + s1,
                                       v2.z + c2 + s2, v2.w + c3 + s3);
}

// ---------------------------------------------------------------------------
extern "C" void kernel_launch(void* const* d_in, const int* in_sizes, int n_in,
                              void* d_out, int out_size) {
    const float* v = (const float*)d_in[0];
    const float* R = (const float*)d_in[1];
    float* out = (float*)d_out;

    const int smF = 4 * STAGE;           // 108544
    const int smMid = MBOFF + 4 * MAST;  // 101376
    const int smInv = 3 * I3STAGE;       // 165888
    cudaFuncSetAttribute(fwd_gemm, cudaFuncAttributeMaxDynamicSharedMemorySize, smF);
    cudaFuncSetAttribute(mid_wmma, cudaFuncAttributeMaxDynamicSharedMemorySize, smMid);
    cudaFuncSetAttribute(inv_gemm, cudaFuncAttributeMaxDynamicSharedMemorySize, smInv);

    prep_all<<<PREP_BLOCKS, 256>>>(v, R);
    fwd_gemm<<<dim3(1, 8, Bb), 512, smF>>>();
    mid_wmma<<<Mm, 256, smMid>>>();
    inv_gemm<<<dim3(2, 16, Bb), 512, smInv>>>(v, out);
    rowQ<<<Bb, 64>>>(v, out);
}

// round 14
// speedup vs baseline: 1.3030x; 1.0143x over previous
#include <cuda_runtime.h>
#include <cuda_fp16.h>
#include <mma.h>
#include <cstdint>

using namespace nvcuda;

#define Bb 32
#define Nn 4096
#define Mm 512
#define Cc 256
#define KF2 1056           // double-folded forward K (0..1024 data, pad to 33*32)

// ---------------------------------------------------------------------------
// Global scratch (static __device__ — no runtime allocation)
// ---------------------------------------------------------------------------
__device__ __align__(16) __half g_Af[(size_t)4 * 256 * KF2];
__device__ __align__(16) __half g_V4[(size_t)Bb * 4 * KF2 * Cc];
__device__ __align__(16) __half g_Ai[(size_t)4 * 1024 * 256];
__device__ __align__(16) __half g_R16[(size_t)Mm * Cc * Cc];
__device__ __align__(16) __half g_Fre16[(size_t)Bb * Mm * Cc];
__device__ __align__(16) __half g_Fim16[(size_t)Bb * Mm * Cc];
__device__ __align__(16) __half g_G4[(size_t)Bb * 4 * 256 * 256];

// ---------------------------------------------------------------------------
__device__ __forceinline__ uint32_t s2u(const void* p) {
    uint32_t a;
    asm("{ .reg .u64 t; cvta.to.shared.u64 t, %1; cvt.u32.u64 %0, t; }"
        : "=r"(a) : "l"(p));
    return a;
}

#define CP16(dst, src) \
    asm volatile("cp.async.cg.shared.global [%0], [%1], 16;" :: "r"(dst), "l"(src))
#define CP_COMMIT() asm volatile("cp.async.commit_group;")
#define CP_WAIT3()  asm volatile("cp.async.wait_group 3;" ::: "memory")
#define CP_WAIT2()  asm volatile("cp.async.wait_group 2;" ::: "memory")
#define CP_WAIT1()  asm volatile("cp.async.wait_group 1;" ::: "memory")
#define CP_WAIT0()  asm volatile("cp.async.wait_group 0;" ::: "memory")

typedef wmma::fragment<wmma::matrix_a, 16, 16, 16, __half, wmma::row_major> FragA;
typedef wmma::fragment<wmma::matrix_b, 16, 16, 16, __half, wmma::row_major> FragB;
typedef wmma::fragment<wmma::accumulator, 16, 16, 16, float> FragC;

// ---------------------------------------------------------------------------
// Fused prep (one launch, permuted block order).
//   [0, 32768)      pack_R
//   [32768, 36992)  genA_fwd
//   [36992, 41088)  genA_inv
//   [41088, 49536)  packV4
// ---------------------------------------------------------------------------
#define PREP_BLOCKS 49536

__global__ __launch_bounds__(256) void prep_all(const float* __restrict__ v,
                                                const float* __restrict__ R) {
    const int tid = threadIdx.x;
    unsigned u = (unsigned)(((unsigned long long)blockIdx.x * 48611ull) % PREP_BLOCKS);

    if (u < 32768u) {
        size_t idx4 = (size_t)u * 256 + tid;
        size_t base = idx4 * 4;
        int m = (int)(base >> 16);
        float sc = (m == 0) ? (1.0f / Nn) : (2.0f / Nn);
        float4 x = *(const float4*)(R + base);
        *(__half2*)(g_R16 + base)     = __half2{__float2half(x.x * sc), __float2half(x.y * sc)};
        *(__half2*)(g_R16 + base + 2) = __half2{__float2half(x.z * sc), __float2half(x.w * sc)};
    } else if (u < 36992u) {
        int idx = (int)(u - 32768u) * 256 + tid;
        int comp = idx / (256 * KF2);
        int rem = idx - comp * (256 * KF2);
        int mp = rem / KF2, k = rem - mp * KF2;
        int m = 2 * mp + (comp & 1);
        float val = 0.0f;
        if (k <= 1024) {
            int t = (int)(((long long)m * k) & (Nn - 1));
            float s, c;
            sincospif((float)t * (1.0f / 2048.0f), &s, &c);
            val = (comp < 2) ? c : -s;
        }
        g_Af[idx] = __float2half(val);
    } else if (u < 41088u) {
        int idx = (int)(u - 36992u) * 256 + tid;
        int comp = idx >> 18;
        int rem = idx & 262143;
        int n = rem >> 8, mp = rem & 255;
        int m = 2 * mp + (comp & 1);
        int t = (int)(((long long)m * n) & (Nn - 1));
        float s, c;
        sincospif((float)t * (1.0f / 2048.0f), &s, &c);
        g_Ai[idx] = __float2half((comp < 2) ? c : s);
    } else {
        size_t idx4 = (size_t)(u - 41088u) * 256 + tid;
        int b = (int)(idx4 / (KF2 * 64));
        int rem = (int)(idx4 - (size_t)b * (KF2 * 64));
        int k = rem >> 6, i = (rem & 63) * 4;
        float4 pp, pm, mm_, mp;
        const float* vb = v + (size_t)b * Nn * Cc;
        if (k == 0) {
            float4 a = *(const float4*)(vb + i);
            float4 d = *(const float4*)(vb + (size_t)2048 * Cc + i);
            pp = make_float4(a.x + d.x, a.y + d.y, a.z + d.z, a.w + d.w);
            pm = make_float4(a.x - d.x, a.y - d.y, a.z - d.z, a.w - d.w);
            mm_ = make_float4(0.f, 0.f, 0.f, 0.f);
            mp = mm_;
        } else if (k < 1024) {
            float4 a = *(const float4*)(vb + (size_t)k * Cc + i);
            float4 bq = *(const float4*)(vb + (size_t)(Nn - k) * Cc + i);
            float4 c = *(const float4*)(vb + (size_t)(2048 - k) * Cc + i);
            float4 d = *(const float4*)(vb + (size_t)(2048 + k) * Cc + i);
            pp = make_float4(a.x + bq.x + c.x + d.x, a.y + bq.y + c.y + d.y,
                             a.z + bq.z + c.z + d.z, a.w + bq.w + c.w + d.w);
            pm = make_float4(a.x + bq.x - c.x - d.x, a.y + bq.y - c.y - d.y,
                             a.z + bq.z - c.z - d.z, a.w + bq.w - c.w - d.w);
            mm_ = make_float4(a.x - bq.x - c.x + d.x, a.y - bq.y - c.y + d.y,
                              a.z - bq.z - c.z + d.z, a.w - bq.w - c.w + d.w);
            mp = make_float4(a.x - bq.x + c.x - d.x, a.y - bq.y + c.y - d.y,
                             a.z - bq.z + c.z - d.z, a.w - bq.w + c.w - d.w);
        } else if (k == 1024) {
            float4 a = *(const float4*)(vb + (size_t)1024 * Cc + i);
            float4 d = *(const float4*)(vb + (size_t)3072 * Cc + i);
            pp = make_float4(a.x + d.x, a.y + d.y, a.z + d.z, a.w + d.w);
            mp = make_float4(a.x - d.x, a.y - d.y, a.z - d.z, a.w - d.w);
            pm = make_float4(0.f, 0.f, 0.f, 0.f);
            mm_ = pm;
        } else {
            pp = make_float4(0.f, 0.f, 0.f, 0.f);
            pm = pp; mm_ = pp; mp = pp;
        }
        size_t pbase = ((size_t)b * 4) * (KF2 * (size_t)Cc) + (size_t)k * Cc + i;
        const size_t PS = (size_t)KF2 * Cc;
        *(__half2*)(g_V4 + pbase)              = __half2{__float2half(pp.x), __float2half(pp.y)};
        *(__half2*)(g_V4 + pbase + 2)          = __half2{__float2half(pp.z), __float2half(pp.w)};
        *(__half2*)(g_V4 + pbase + PS)         = __half2{__float2half(pm.x), __float2half(pm.y)};
        *(__half2*)(g_V4 + pbase + PS + 2)     = __half2{__float2half(pm.z), __float2half(pm.w)};
        *(__half2*)(g_V4 + pbase + 2 * PS)     = __half2{__float2half(mm_.x), __float2half(mm_.y)};
        *(__half2*)(g_V4 + pbase + 2 * PS + 2) = __half2{__float2half(mm_.z), __float2half(mm_.w)};
        *(__half2*)(g_V4 + pbase + 3 * PS)     = __half2{__float2half(mp.x), __float2half(mp.y)};
        *(__half2*)(g_V4 + pbase + 3 * PS + 2) = __half2{__float2half(mp.z), __float2half(mp.w)};
    }
}

// ---------------------------------------------------------------------------
// Forward WMMA GEMM (double-folded, unchanged). CTA 128(m') x 256(i),
// 512 threads, warp tile 32x64, 4-stage cp.async, K=1056.
// ---------------------------------------------------------------------------
#define STAGE 27136

__global__ __launch_bounds__(512) void fwd_gemm() {
    extern __shared__ __align__(16) char sm[];
    const uint32_t sb = s2u(sm);
    const int tid = threadIdx.x;
    const int warp = tid >> 5, lane = tid & 31;
    const int wm = warp >> 2, wn = warp & 3;
    const int b = blockIdx.z;
    const int y = blockIdx.y;
    const int comp = y >> 1, yt = y & 1;
    const int par = comp & 1;

    const __half* Ap = g_Af + (size_t)comp * 256 * KF2;
    const __half* Bp = g_V4 + ((size_t)b * 4 + comp) * ((size_t)KF2 * Cc);
    __half* Fout = (comp < 2) ? g_Fre16 : g_Fim16;
    const int row0 = yt * 128;
    const int NCH = KF2 / 32;

    FragC acc[2][4];
    #pragma unroll
    for (int a = 0; a < 2; a++)
        #pragma unroll
        for (int j = 0; j < 4; j++) wmma::fill_fragment(acc[a][j], 0.0f);

    const int ar = tid >> 2, aq = tid & 3;
    const int br = tid >> 4, bs = tid & 15;

    auto load = [&](int stage, int k0) {
        uint32_t s0 = sb + stage * STAGE;
        size_t ga = (size_t)(row0 + ar) * KF2 + k0 + aq * 8;
        CP16(s0 + ar * 80 + aq * 16, Ap + ga);
        size_t gb = (size_t)(k0 + br) * Cc + bs * 8;
        uint32_t bd = s0 + 10240 + br * 528 + bs * 16;
        CP16(bd, Bp + gb);
        CP16(bd + 256, Bp + gb + 128);
        CP_COMMIT();
    };

    load(0, 0);
    load(1, 32);
    load(2, 64);

    int stage = 0;
    for (int c = 0; c < NCH; c++) {
        if (c + 3 < NCH) {
            int ns = stage + 3; if (ns >= 4) ns -= 4;
            load(ns, (c + 3) * 32);
            CP_WAIT3();
        } else if (c + 2 < NCH) {
            CP_WAIT2();
        } else if (c + 1 < NCH) {
            CP_WAIT1();
        } else {
            CP_WAIT0();
        }
        __syncthreads();

        const char* base = sm + stage * STAGE;
        const __half* As = (const __half*)(base);
        const __half* Bs = (const __half*)(base + 10240);

        #pragma unroll
        for (int ks = 0; ks < 2; ks++) {
            const int kk = ks * 16;
            FragB bf[4];
            #pragma unroll
            for (int j = 0; j < 4; j++)
                wmma::load_matrix_sync(bf[j], Bs + kk * 264 + wn * 64 + j * 16, 264);
            #pragma unroll
            for (int ms = 0; ms < 2; ms++) {
                FragA af;
                wmma::load_matrix_sync(af, As + (wm * 32 + ms * 16) * 40 + kk, 40);
                #pragma unroll
                for (int j = 0; j < 4; j++)
                    wmma::mma_sync(acc[ms][j], af, bf[j], acc[ms][j]);
            }
        }
        __syncthreads();
        stage++; if (stage >= 4) stage = 0;
    }

    float* patch = (float*)sm + warp * 1088;
    #pragma unroll
    for (int ms = 0; ms < 2; ms++) {
        #pragma unroll
        for (int j = 0; j < 4; j++)
            wmma::store_matrix_sync(patch + j * 16, acc[ms][j], 68, wmma::mem_row_major);
        __syncwarp();
        int mpbase = row0 + wm * 32 + ms * 16;
        #pragma unroll
        for (int rr = 0; rr < 16; rr++) {
            float x0 = patch[rr * 68 + lane * 2];
            float x1 = patch[rr * 68 + lane * 2 + 1];
            int m = 2 * (mpbase + rr) + par;
            *(__half2*)(Fout + ((size_t)b * Mm + m) * Cc + wn * 64 + lane * 2)
                = __half2{__float2half(x0), __float2half(x1)};
        }
        __syncwarp();
    }
}

// ---------------------------------------------------------------------------
// Mid WMMA (unchanged).
// ---------------------------------------------------------------------------
#define MAST 16896
#define MBOFF 33792

__global__ __launch_bounds__(256, 2) void mid_wmma() {
    extern __shared__ __align__(16) char sm[];
    const uint32_t sb = s2u(sm);
    const int tid = threadIdx.x;
    const int warp = tid >> 5, lane = tid & 31;
    const int m = blockIdx.x;

    __half* Are = (__half*)sm;
    __half* Aim = (__half*)(sm + MAST);

    #pragma unroll
    for (int it = 0; it < 8; it++) {
        int idx = tid + 256 * it;
        int plane = idx >> 10, rem = idx & 1023;
        int row = rem >> 5, seg = rem & 31;
        const __half* src = (plane ? g_Fim16 : g_Fre16)
                            + ((size_t)row * Mm + m) * Cc + seg * 8;
        uint32_t dst = sb + plane * MAST + row * 528 + seg * 16;
        CP16(dst, src);
    }
    CP_COMMIT();

    const int kr = tid >> 3, seg = tid & 7;
    auto loadB = [&](int stage, int c) {
        uint32_t s0 = sb + MBOFF + stage * MAST;
        size_t gb = ((size_t)m * Cc + c * 32 + kr) * Cc + seg * 32;
        uint32_t bd = s0 + kr * 528 + seg * 64;
        CP16(bd,      g_R16 + gb);
        CP16(bd + 16, g_R16 + gb + 8);
        CP16(bd + 32, g_R16 + gb + 16);
        CP16(bd + 48, g_R16 + gb + 24);
        CP_COMMIT();
    };

    loadB(0, 0);
    loadB(1, 1);
    loadB(2, 2);

    FragC accR[2][2], accI[2][2];
    #pragma unroll
    for (int a = 0; a < 2; a++)
        #pragma unroll
        for (int j = 0; j < 2; j++) {
            wmma::fill_fragment(accR[a][j], 0.0f);
            wmma::fill_fragment(accI[a][j], 0.0f);
        }

    int stage = 0;
    for (int c = 0; c < 8; c++) {
        if (c + 3 < 8) {
            int ns = stage + 3; if (ns >= 4) ns -= 4;
            loadB(ns, c + 3);
            CP_WAIT3();
        } else if (c + 2 < 8) {
            CP_WAIT2();
        } else if (c + 1 < 8) {
            CP_WAIT1();
        } else {
            CP_WAIT0();
        }
        __syncthreads();

        const __half* Bs = (const __half*)(sm + MBOFF + stage * MAST);
        #pragma unroll
        for (int ks = 0; ks < 2; ks++) {
            const int kk = c * 32 + ks * 16;
            FragB bf[2];
            #pragma unroll
            for (int j = 0; j < 2; j++)
                wmma::load_matrix_sync(bf[j], Bs + (ks * 16) * 264 + warp * 32 + j * 16, 264);
            #pragma unroll
            for (int ms = 0; ms < 2; ms++) {
                FragA ar_, ai_;
                wmma::load_matrix_sync(ar_, Are + ms * 16 * 264 + kk, 264);
                wmma::load_matrix_sync(ai_, Aim + ms * 16 * 264 + kk, 264);
                #pragma unroll
                for (int j = 0; j < 2; j++) {
                    wmma::mma_sync(accR[ms][j], ar_, bf[j], accR[ms][j]);
                    wmma::mma_sync(accI[ms][j], ai_, bf[j], accI[ms][j]);
                }
            }
        }
        __syncthreads();
        stage++; if (stage >= 4) stage = 0;
    }

    float* bre = (float*)sm + warp * 2560;
    float* bim = bre + 1280;
    #pragma unroll
    for (int ms = 0; ms < 2; ms++)
        #pragma unroll
        for (int j = 0; j < 2; j++) {
            wmma::store_matrix_sync(bre + ms * 16 * 40 + j * 16, accR[ms][j], 40, wmma::mem_row_major);
            wmma::store_matrix_sync(bim + ms * 16 * 40 + j * 16, accI[ms][j], 40, wmma::mem_row_major);
        }
    __syncwarp();
    const int preP = m & 1;
    const int pimP = 2 + (m & 1);
    const int mrow = m >> 1;
    #pragma unroll 4
    for (int r = 0; r < 32; r++) {
        size_t gre = (((size_t)r * 4 + preP) * 256 + mrow) * Cc + warp * 32 + lane;
        size_t gim = (((size_t)r * 4 + pimP) * 256 + mrow) * Cc + warp * 32 + lane;
        g_G4[gre] = __float2half(bre[r * 40 + lane]);
        g_G4[gim] = __float2half(bim[r * 40 + lane]);
    }
}

// ---------------------------------------------------------------------------
// Inverse WMMA GEMM, persistent over batches, A (twiddles) smem-resident.
// CTA 64(n) x 128(o), 512 threads, 16 warps; loops over 8 batches.
// comp = warp>>2: 0 Ce, 1 Co, 2 Se, 3 So; warp tile 32x64 per comp.
// smem: A 4x[64 rows x 264 elem] @0 (135168B, loaded once);
//       B 2 stages x (4 x [32 x 136 elem]) @135168 (34816B each);
//       epilogue bufs 4 x [64x68 fp32] overlap the B region (69632B).
// Epilogue per batch (two 64-col halves):
//   out[n] = v + (Ce+Co) - (Se+So);  out[4096-n] = v + (Ce+Co) + (Se+So) (n>0)
//   out[2048-n] = v + (Ce-Co) + (Se-So);  out[2048+n] = v + (Ce-Co) - (Se-So) (n>0)
// grid: (2 colt, 16 yt, 4 bg) = 128 CTAs; b = bg*8 + bi.
// ---------------------------------------------------------------------------
#define IA_BYTES 135168
#define IB_STAGE 34816

__global__ __launch_bounds__(512) void inv_gemm(const float* __restrict__ v,
                                                float* __restrict__ out) {
    extern __shared__ __align__(16) char sm[];
    const uint32_t sb = s2u(sm);
    const int tid = threadIdx.x;
    const int warp = tid >> 5;
    const int comp = warp >> 2;
    const int w4 = warp & 3;
    const int wm = w4 >> 1, wn = w4 & 1;
    const int colt = blockIdx.x, yt = blockIdx.y, bg = blockIdx.z;
    const int row0 = yt * 64, c0 = colt * 128;

    // ---- Load resident A: 4 comps x 64 rows x 256 K (row stride 264 elem) ----
    #pragma unroll
    for (int it = 0; it < 16; it++) {
        int idx = tid + 512 * it;               // 8192 CP16 total
        int c = idx >> 11;
        int rem = idx & 2047;
        int r = rem >> 5, seg = rem & 31;
        size_t ga = ((size_t)c << 18) + (size_t)(row0 + r) * 256 + seg * 8;
        uint32_t ad = sb + c * 33792 + r * 528 + seg * 16;
        CP16(ad, g_Ai + ga);
    }
    CP_COMMIT();

    const __half* Asm = (const __half*)sm + comp * 16896;   // elems

    // B loader: per chunk, 4 comps x 32 rows x 16 segs = 2048 CP16 / 512 thr
    const int bc = tid >> 9;  // unused split helper (kept simple below)
    auto loadB = [&](int stage, int b, int k0) {
        uint32_t s0 = sb + IA_BYTES + stage * IB_STAGE;
        #pragma unroll
        for (int it = 0; it < 4; it++) {
            int idx = tid + 512 * it;
            int c = idx >> 9;
            int rem = idx & 511;
            int r = rem >> 4, seg = rem & 15;
            size_t gb = (((size_t)b * 4 + c) * 256 + k0 + r) * Cc + c0 + seg * 8;
            uint32_t bd = s0 + c * 8704 + r * 272 + seg * 16;
            CP16(bd, g_G4 + gb);
        }
        CP_COMMIT();
    };

    for (int bi = 0; bi < 8; bi++) {
        const int b = bg * 8 + bi;

        FragC acc[2][4];
        #pragma unroll
        for (int a = 0; a < 2; a++)
            #pragma unroll
            for (int j = 0; j < 4; j++) wmma::fill_fragment(acc[a][j], 0.0f);

        loadB(0, b, 0);
        loadB(1, b, 32);

        for (int c = 0; c < 8; c++) {
            if (c < 7) { CP_WAIT1(); } else { CP_WAIT0(); }
            __syncthreads();

            const int stg = c & 1;
            const __half* Bs = (const __half*)(sm + IA_BYTES + stg * IB_STAGE
                                               + comp * 8704);
            #pragma unroll
            for (int ks = 0; ks < 2; ks++) {
                const int kk = ks * 16;
                FragB bf[4];
                #pragma unroll
                for (int j = 0; j < 4; j++)
                    wmma::load_matrix_sync(bf[j], Bs + kk * 136 + wn * 64 + j * 16, 136);
                #pragma unroll
                for (int ms = 0; ms < 2; ms++) {
                    FragA af;
                    wmma::load_matrix_sync(af, Asm + (wm * 32 + ms * 16) * 264
                                               + c * 32 + kk, 264);
                    #pragma unroll
                    for (int j = 0; j < 4; j++)
                        wmma::mma_sync(acc[ms][j], af, bf[j], acc[ms][j]);
                }
            }
            __syncthreads();
            if (c + 2 < 8) loadB(stg, b, (c + 2) * 32);
        }

        // ---- Epilogue: two 64-col halves through fp32 bufs (overlap B region)
        float* bufs = (float*)(sm + IA_BYTES);
        float* buf = bufs + comp * 4352;        // 64 x 68 fp32
        const float* Ceb = bufs;
        const float* Cob = bufs + 4352;
        const float* Seb = bufs + 8704;
        const float* Sob = bufs + 13056;
        const size_t rowb = (size_t)b * Nn;

        #pragma unroll
        for (int h = 0; h < 2; h++) {
            if (wn == h) {
                #pragma unroll
                for (int ms = 0; ms < 2; ms++)
                    #pragma unroll
                    for (int j = 0; j < 4; j++)
                        wmma::store_matrix_sync(buf + (wm * 32 + ms * 16) * 68 + j * 16,
                                                acc[ms][j], 68, wmma::mem_row_major);
            }
            __syncthreads();

            #pragma unroll
            for (int it = 0; it < 2; it++) {
                int idx = tid + 512 * it;        // 0..1023: 64 rows x 16 float4
                int r = idx >> 4, c4 = idx & 15;
                int off = r * 68 + c4 * 4;
                float4 Ce = *(const float4*)(Ceb + off);
                float4 Co = *(const float4*)(Cob + off);
                float4 Se = *(const float4*)(Seb + off);
                float4 So = *(const float4*)(Sob + off);
                float4 A1 = make_float4(Ce.x + Co.x, Ce.y + Co.y, Ce.z + Co.z, Ce.w + Co.w);
                float4 A2 = make_float4(Se.x + So.x, Se.y + So.y, Se.z + So.z, Se.w + So.w);
                float4 A3 = make_float4(Ce.x - Co.x, Ce.y - Co.y, Ce.z - Co.z, Ce.w - Co.w);
                float4 A4 = make_float4(Se.x - So.x, Se.y - So.y, Se.z - So.z, Se.w - So.w);
                int n = row0 + r;
                int o = c0 + h * 64 + c4 * 4;
                {
                    size_t i1 = (rowb + n) * Cc + o;
                    float4 vv = *(const float4*)(v + i1);
                    *(float4*)(out + i1) = make_float4(vv.x + A1.x - A2.x, vv.y + A1.y - A2.y,
                                                       vv.z + A1.z - A2.z, vv.w + A1.w - A2.w);
                }
                if (n > 0) {
                    size_t i2 = (rowb + (Nn - n)) * Cc + o;
                    float4 vv = *(const float4*)(v + i2);
                    *(float4*)(out + i2) = make_float4(vv.x + A1.x + A2.x, vv.y + A1.y + A2.y,
                                                       vv.z + A1.z + A2.z, vv.w + A1.w + A2.w);
                }
                {
                    size_t i3 = (rowb + (2048 - n)) * Cc + o;
                    float4 vv = *(const float4*)(v + i3);
                    *(float4*)(out + i3) = make_float4(vv.x + A3.x + A4.x, vv.y + A3.y + A4.y,
                                                       vv.z + A3.z + A4.z, vv.w + A3.w + A4.w);
                }
                if (n > 0) {
                    size_t i4 = (rowb + (2048 + n)) * Cc + o;
                    float4 vv = *(const float4*)(v + i4);
                    *(float4*)(out + i4) = make_float4(vv.x + A3.x - A4.x, vv.y + A3.y - A4.y,
                                                       vv.z + A3.z - A4.z, vv.w + A3.w - A4.w);
                }
            }
            __syncthreads();
        }
    }
}

// ---------------------------------------------------------------------------
// rowQ: n = 1024. out[1024] = v + C - S;  out[3072] = v + C + S.
// ---------------------------------------------------------------------------
__global__ __launch_bounds__(64) void rowQ(const float* __restrict__ v,
                                           float* __restrict__ out) {
    const int b = blockIdx.x;
    const int o = threadIdx.x * 4;
    float c0 = 0.f, c1 = 0.f, c2 = 0.f, c3 = 0.f;
    float s0 = 0.f, s1 = 0.f, s2 = 0.f, s3 = 0.f;
    const __half* GreE = g_G4 + ((size_t)b * 4 + 0) * 65536;
    const __half* GimO = g_G4 + ((size_t)b * 4 + 3) * 65536;
    #pragma unroll 8
    for (int mp = 0; mp < 256; mp++) {
        float sgn = (mp & 1) ? -1.0f : 1.0f;
        const __half* gr = GreE + (size_t)mp * Cc + o;
        const __half* gi = GimO + (size_t)mp * Cc + o;
        __half2 ra = *(const __half2*)(gr), rb = *(const __half2*)(gr + 2);
        __half2 ia = *(const __half2*)(gi), ib = *(const __half2*)(gi + 2);
        c0 += sgn * __half2float(ra.x); c1 += sgn * __half2float(ra.y);
        c2 += sgn * __half2float(rb.x); c3 += sgn * __half2float(rb.y);
        s0 += sgn * __half2float(ia.x); s1 += sgn * __half2float(ia.y);
        s2 += sgn * __half2float(ib.x); s3 += sgn * __half2float(ib.y);
    }
    size_t i1 = ((size_t)b * Nn + 1024) * Cc + o;
    size_t i2 = ((size_t)b * Nn + 3072) * Cc + o;
    float4 v1 = *(const float4*)(v + i1);
    float4 v2 = *(const float4*)(v + i2);
    *(float4*)(out + i1) = make_float4(v1.x + c0 - s0, v1.y + c1 - s1,
                                       v1.z + c2 - s2, v1.w + c3 - s3);
    *(float4*)(out + i2) = make_float4(v2.x + c0 + s0, v2.y + c1 + s1,
                                       v2.z + c2 + s2, v2.w + c3 + s3);
}

// ---------------------------------------------------------------------------
extern "C" void kernel_launch(void* const* d_in, const int* in_sizes, int n_in,
                              void* d_out, int out_size) {
    const float* v = (const float*)d_in[0];
    const float* R = (const float*)d_in[1];
    float* out = (float*)d_out;

    const int smF = 4 * STAGE;              // 108544
    const int smMid = MBOFF + 4 * MAST;     // 101376
    const int smInv = IA_BYTES + 69632;     // 204800
    cudaFuncSetAttribute(fwd_gemm, cudaFuncAttributeMaxDynamicSharedMemorySize, smF);
    cudaFuncSetAttribute(mid_wmma, cudaFuncAttributeMaxDynamicSharedMemorySize, smMid);
    cudaFuncSetAttribute(inv_gemm, cudaFuncAttributeMaxDynamicSharedMemorySize, smInv);

    prep_all<<<PREP_BLOCKS, 256>>>(v, R);
    fwd_gemm<<<dim3(1, 8, Bb), 512, smF>>>();
    mid_wmma<<<Mm, 256, smMid>>>();
    inv_gemm<<<dim3(2, 16, 4), 512, smInv>>>(v, out);
    rowQ<<<Bb, 64>>>(v, out);
}

// round 15
// speedup vs baseline: 1.3124x; 1.0073x over previous
#include <cuda_runtime.h>
#include <cuda_fp16.h>
#include <mma.h>
#include <cstdint>

using namespace nvcuda;

#define Bb 32
#define Nn 4096
#define Mm 512
#define Cc 256
#define KF2 1056           // double-folded forward K (0..1024 data, pad to 33*32)

// ---------------------------------------------------------------------------
// Global scratch (static __device__ — no runtime allocation)
// ---------------------------------------------------------------------------
__device__ __align__(16) __half g_Af[(size_t)4 * 256 * KF2];
__device__ __align__(16) __half g_V4[(size_t)Bb * 4 * KF2 * Cc];
__device__ __align__(16) __half g_Ai[(size_t)4 * 1024 * 256];
__device__ __align__(16) __half g_Fre16[(size_t)Bb * Mm * Cc];
__device__ __align__(16) __half g_Fim16[(size_t)Bb * Mm * Cc];
__device__ __align__(16) __half g_G4[(size_t)Bb * 4 * 256 * 256];

// ---------------------------------------------------------------------------
__device__ __forceinline__ uint32_t s2u(const void* p) {
    uint32_t a;
    asm("{ .reg .u64 t; cvta.to.shared.u64 t, %1; cvt.u32.u64 %0, t; }"
        : "=r"(a) : "l"(p));
    return a;
}

#define CP16(dst, src) \
    asm volatile("cp.async.cg.shared.global [%0], [%1], 16;" :: "r"(dst), "l"(src))
#define CP_COMMIT() asm volatile("cp.async.commit_group;")
#define CP_WAIT3()  asm volatile("cp.async.wait_group 3;" ::: "memory")
#define CP_WAIT2()  asm volatile("cp.async.wait_group 2;" ::: "memory")
#define CP_WAIT1()  asm volatile("cp.async.wait_group 1;" ::: "memory")
#define CP_WAIT0()  asm volatile("cp.async.wait_group 0;" ::: "memory")

typedef wmma::fragment<wmma::matrix_a, 16, 16, 16, __half, wmma::row_major> FragA;
typedef wmma::fragment<wmma::matrix_b, 16, 16, 16, __half, wmma::row_major> FragB;
typedef wmma::fragment<wmma::accumulator, 16, 16, 16, float> FragC;

// ---------------------------------------------------------------------------
// Fused prep (one launch, permuted block order; pack_R removed).
//   [0, 4224)       genA_fwd
//   [4224, 8320)    genA_inv
//   [8320, 16768)   packV4
// ---------------------------------------------------------------------------
#define PREP_BLOCKS 16768

__global__ __launch_bounds__(256) void prep_all(const float* __restrict__ v) {
    const int tid = threadIdx.x;
    unsigned u = (unsigned)(((unsigned long long)blockIdx.x * 9871ull) % PREP_BLOCKS);

    if (u < 4224u) {
        // ---- genA_fwd: [comp][m'][k]; comp: 0 cos_e, 1 cos_o, 2 -sin_e, 3 -sin_o
        int idx = (int)u * 256 + tid;
        int comp = idx / (256 * KF2);
        int rem = idx - comp * (256 * KF2);
        int mp = rem / KF2, k = rem - mp * KF2;
        int m = 2 * mp + (comp & 1);
        float val = 0.0f;
        if (k <= 1024) {
            int t = (int)(((long long)m * k) & (Nn - 1));
            float s, c;
            sincospif((float)t * (1.0f / 2048.0f), &s, &c);
            val = (comp < 2) ? c : -s;
        }
        g_Af[idx] = __float2half(val);
    } else if (u < 8320u) {
        // ---- genA_inv: [comp][n][m']; comp: 0 cos_e, 1 cos_o, 2 sin_e, 3 sin_o
        int idx = (int)(u - 4224u) * 256 + tid;
        int comp = idx >> 18;
        int rem = idx & 262143;
        int n = rem >> 8, mp = rem & 255;
        int m = 2 * mp + (comp & 1);
        int t = (int)(((long long)m * n) & (Nn - 1));
        float s, c;
        sincospif((float)t * (1.0f / 2048.0f), &s, &c);
        g_Ai[idx] = __float2half((comp < 2) ? c : s);
    } else {
        // ---- packV4: vpp, vpm, vmm, vmp (double fold) ----
        size_t idx4 = (size_t)(u - 8320u) * 256 + tid;
        int b = (int)(idx4 / (KF2 * 64));
        int rem = (int)(idx4 - (size_t)b * (KF2 * 64));
        int k = rem >> 6, i = (rem & 63) * 4;
        float4 pp, pm, mm_, mp;
        const float* vb = v + (size_t)b * Nn * Cc;
        if (k == 0) {
            float4 a = *(const float4*)(vb + i);
            float4 d = *(const float4*)(vb + (size_t)2048 * Cc + i);
            pp = make_float4(a.x + d.x, a.y + d.y, a.z + d.z, a.w + d.w);
            pm = make_float4(a.x - d.x, a.y - d.y, a.z - d.z, a.w - d.w);
            mm_ = make_float4(0.f, 0.f, 0.f, 0.f);
            mp = mm_;
        } else if (k < 1024) {
            float4 a = *(const float4*)(vb + (size_t)k * Cc + i);
            float4 bq = *(const float4*)(vb + (size_t)(Nn - k) * Cc + i);
            float4 c = *(const float4*)(vb + (size_t)(2048 - k) * Cc + i);
            float4 d = *(const float4*)(vb + (size_t)(2048 + k) * Cc + i);
            pp = make_float4(a.x + bq.x + c.x + d.x, a.y + bq.y + c.y + d.y,
                             a.z + bq.z + c.z + d.z, a.w + bq.w + c.w + d.w);
            pm = make_float4(a.x + bq.x - c.x - d.x, a.y + bq.y - c.y - d.y,
                             a.z + bq.z - c.z - d.z, a.w + bq.w - c.w - d.w);
            mm_ = make_float4(a.x - bq.x - c.x + d.x, a.y - bq.y - c.y + d.y,
                              a.z - bq.z - c.z + d.z, a.w - bq.w - c.w + d.w);
            mp = make_float4(a.x - bq.x + c.x - d.x, a.y - bq.y + c.y - d.y,
                             a.z - bq.z + c.z - d.z, a.w - bq.w + c.w - d.w);
        } else if (k == 1024) {
            float4 a = *(const float4*)(vb + (size_t)1024 * Cc + i);
            float4 d = *(const float4*)(vb + (size_t)3072 * Cc + i);
            pp = make_float4(a.x + d.x, a.y + d.y, a.z + d.z, a.w + d.w);
            mp = make_float4(a.x - d.x, a.y - d.y, a.z - d.z, a.w - d.w);
            pm = make_float4(0.f, 0.f, 0.f, 0.f);
            mm_ = pm;
        } else {
            pp = make_float4(0.f, 0.f, 0.f, 0.f);
            pm = pp; mm_ = pp; mp = pp;
        }
        size_t pbase = ((size_t)b * 4) * (KF2 * (size_t)Cc) + (size_t)k * Cc + i;
        const size_t PS = (size_t)KF2 * Cc;
        *(__half2*)(g_V4 + pbase)              = __half2{__float2half(pp.x), __float2half(pp.y)};
        *(__half2*)(g_V4 + pbase + 2)          = __half2{__float2half(pp.z), __float2half(pp.w)};
        *(__half2*)(g_V4 + pbase + PS)         = __half2{__float2half(pm.x), __float2half(pm.y)};
        *(__half2*)(g_V4 + pbase + PS + 2)     = __half2{__float2half(pm.z), __float2half(pm.w)};
        *(__half2*)(g_V4 + pbase + 2 * PS)     = __half2{__float2half(mm_.x), __float2half(mm_.y)};
        *(__half2*)(g_V4 + pbase + 2 * PS + 2) = __half2{__float2half(mm_.z), __float2half(mm_.w)};
        *(__half2*)(g_V4 + pbase + 3 * PS)     = __half2{__float2half(mp.x), __float2half(mp.y)};
        *(__half2*)(g_V4 + pbase + 3 * PS + 2) = __half2{__float2half(mp.z), __float2half(mp.w)};
    }
}

// ---------------------------------------------------------------------------
// Forward WMMA GEMM (double-folded, unchanged). CTA 128(m') x 256(i),
// 512 threads, warp tile 32x64, 4-stage cp.async, K=1056.
// ---------------------------------------------------------------------------
#define STAGE 27136

__global__ __launch_bounds__(512) void fwd_gemm() {
    extern __shared__ __align__(16) char sm[];
    const uint32_t sb = s2u(sm);
    const int tid = threadIdx.x;
    const int warp = tid >> 5, lane = tid & 31;
    const int wm = warp >> 2, wn = warp & 3;
    const int b = blockIdx.z;
    const int y = blockIdx.y;
    const int comp = y >> 1, yt = y & 1;
    const int par = comp & 1;

    const __half* Ap = g_Af + (size_t)comp * 256 * KF2;
    const __half* Bp = g_V4 + ((size_t)b * 4 + comp) * ((size_t)KF2 * Cc);
    __half* Fout = (comp < 2) ? g_Fre16 : g_Fim16;
    const int row0 = yt * 128;
    const int NCH = KF2 / 32;

    FragC acc[2][4];
    #pragma unroll
    for (int a = 0; a < 2; a++)
        #pragma unroll
        for (int j = 0; j < 4; j++) wmma::fill_fragment(acc[a][j], 0.0f);

    const int ar = tid >> 2, aq = tid & 3;
    const int br = tid >> 4, bs = tid & 15;

    auto load = [&](int stage, int k0) {
        uint32_t s0 = sb + stage * STAGE;
        size_t ga = (size_t)(row0 + ar) * KF2 + k0 + aq * 8;
        CP16(s0 + ar * 80 + aq * 16, Ap + ga);
        size_t gb = (size_t)(k0 + br) * Cc + bs * 8;
        uint32_t bd = s0 + 10240 + br * 528 + bs * 16;
        CP16(bd, Bp + gb);
        CP16(bd + 256, Bp + gb + 128);
        CP_COMMIT();
    };

    load(0, 0);
    load(1, 32);
    load(2, 64);

    int stage = 0;
    for (int c = 0; c < NCH; c++) {
        if (c + 3 < NCH) {
            int ns = stage + 3; if (ns >= 4) ns -= 4;
            load(ns, (c + 3) * 32);
            CP_WAIT3();
        } else if (c + 2 < NCH) {
            CP_WAIT2();
        } else if (c + 1 < NCH) {
            CP_WAIT1();
        } else {
            CP_WAIT0();
        }
        __syncthreads();

        const char* base = sm + stage * STAGE;
        const __half* As = (const __half*)(base);
        const __half* Bs = (const __half*)(base + 10240);

        #pragma unroll
        for (int ks = 0; ks < 2; ks++) {
            const int kk = ks * 16;
            FragB bf[4];
            #pragma unroll
            for (int j = 0; j < 4; j++)
                wmma::load_matrix_sync(bf[j], Bs + kk * 264 + wn * 64 + j * 16, 264);
            #pragma unroll
            for (int ms = 0; ms < 2; ms++) {
                FragA af;
                wmma::load_matrix_sync(af, As + (wm * 32 + ms * 16) * 40 + kk, 40);
                #pragma unroll
                for (int j = 0; j < 4; j++)
                    wmma::mma_sync(acc[ms][j], af, bf[j], acc[ms][j]);
            }
        }
        __syncthreads();
        stage++; if (stage >= 4) stage = 0;
    }

    float* patch = (float*)sm + warp * 1088;
    #pragma unroll
    for (int ms = 0; ms < 2; ms++) {
        #pragma unroll
        for (int j = 0; j < 4; j++)
            wmma::store_matrix_sync(patch + j * 16, acc[ms][j], 68, wmma::mem_row_major);
        __syncwarp();
        int mpbase = row0 + wm * 32 + ms * 16;
        #pragma unroll
        for (int rr = 0; rr < 16; rr++) {
            float x0 = patch[rr * 68 + lane * 2];
            float x1 = patch[rr * 68 + lane * 2 + 1];
            int m = 2 * (mpbase + rr) + par;
            *(__half2*)(Fout + ((size_t)b * Mm + m) * Cc + wn * 64 + lane * 2)
                = __half2{__float2half(x0), __float2half(x1)};
        }
        __syncwarp();
    }
}

// ---------------------------------------------------------------------------
// Mid WMMA: per mode m, G[32b, 256o] = F[32b, 256i] @ (R[m]*w_m/N) (re & im).
// 256 threads, 8 warps, warp tile 32x32. R read fp32 directly from input and
// converted in-register (pack_R eliminated). B: 2 smem stages, reg-buffered
// one chunk ahead (8 float4/thread in flight).
// smem: A_re[32][264] @0 (16896), A_im @16896, B stages @33792, @50688;
// epilogue bounce (81920B) overlaps everything at offset 0.
// ---------------------------------------------------------------------------
#define MAST 16896
#define MBOFF 33792

__global__ __launch_bounds__(256, 2) void mid_wmma(const float* __restrict__ R) {
    extern __shared__ __align__(16) char sm[];
    const uint32_t sb = s2u(sm);
    const int tid = threadIdx.x;
    const int warp = tid >> 5, lane = tid & 31;
    const int m = blockIdx.x;
    const float sc = (m == 0) ? (1.0f / Nn) : (2.0f / Nn);

    __half* Are = (__half*)sm;
    __half* Aim = (__half*)(sm + MAST);

    // A loader (F fp16, both comps) via cp.async — one group.
    #pragma unroll
    for (int it = 0; it < 8; it++) {
        int idx = tid + 256 * it;
        int plane = idx >> 10, rem = idx & 1023;
        int row = rem >> 5, seg = rem & 31;
        const __half* src = (plane ? g_Fim16 : g_Fre16)
                            + ((size_t)row * Mm + m) * Cc + seg * 8;
        uint32_t dst = sb + plane * MAST + row * 528 + seg * 16;
        CP16(dst, src);
    }
    CP_COMMIT();

    // B: thread (kr, seg) handles row kr, cols seg*32..seg*32+31 (8 float4).
    const int kr = tid >> 3, seg = tid & 7;
    const float* Rm = R + (size_t)m * Cc * Cc;
    float4 rbuf[8];

    auto loadB_regs = [&](int c) {
        const float* src = Rm + (size_t)(c * 32 + kr) * Cc + seg * 32;
        #pragma unroll
        for (int j = 0; j < 8; j++) rbuf[j] = *(const float4*)(src + j * 4);
    };
    auto storeB = [&](int stg) {
        __half* dst = (__half*)(sm + MBOFF + stg * MAST) + kr * 264 + seg * 32;
        #pragma unroll
        for (int j = 0; j < 8; j++) {
            *(__half2*)(dst + j * 4)     = __half2{__float2half(rbuf[j].x * sc),
                                                   __float2half(rbuf[j].y * sc)};
            *(__half2*)(dst + j * 4 + 2) = __half2{__float2half(rbuf[j].z * sc),
                                                   __float2half(rbuf[j].w * sc)};
        }
    };

    loadB_regs(0);
    storeB(0);
    loadB_regs(1);

    FragC accR[2][2], accI[2][2];
    #pragma unroll
    for (int a = 0; a < 2; a++)
        #pragma unroll
        for (int j = 0; j < 2; j++) {
            wmma::fill_fragment(accR[a][j], 0.0f);
            wmma::fill_fragment(accI[a][j], 0.0f);
        }

    CP_WAIT0();          // A resident
    __syncthreads();     // stage 0 B visible

    for (int c = 0; c < 8; c++) {
        // Write next chunk's B to the OTHER stage (free since iter c-1's sync),
        // then compute this chunk, then prefetch chunk c+2 into registers.
        if (c + 1 < 8) storeB((c + 1) & 1);

        const __half* Bs = (const __half*)(sm + MBOFF + (c & 1) * MAST);
        #pragma unroll
        for (int ks = 0; ks < 2; ks++) {
            const int kk = c * 32 + ks * 16;
            FragB bf[2];
            #pragma unroll
            for (int j = 0; j < 2; j++)
                wmma::load_matrix_sync(bf[j], Bs + (ks * 16) * 264 + warp * 32 + j * 16, 264);
            #pragma unroll
            for (int ms = 0; ms < 2; ms++) {
                FragA ar_, ai_;
                wmma::load_matrix_sync(ar_, Are + ms * 16 * 264 + kk, 264);
                wmma::load_matrix_sync(ai_, Aim + ms * 16 * 264 + kk, 264);
                #pragma unroll
                for (int j = 0; j < 2; j++) {
                    wmma::mma_sync(accR[ms][j], ar_, bf[j], accR[ms][j]);
                    wmma::mma_sync(accI[ms][j], ai_, bf[j], accI[ms][j]);
                }
            }
        }
        if (c + 2 < 8) loadB_regs(c + 2);
        __syncthreads();
    }

    // Epilogue bounce at sm+0 (A/B regions dead), fp16 plane writes to g_G4.
    float* bre = (float*)sm + warp * 2560;
    float* bim = bre + 1280;
    #pragma unroll
    for (int ms = 0; ms < 2; ms++)
        #pragma unroll
        for (int j = 0; j < 2; j++) {
            wmma::store_matrix_sync(bre + ms * 16 * 40 + j * 16, accR[ms][j], 40, wmma::mem_row_major);
            wmma::store_matrix_sync(bim + ms * 16 * 40 + j * 16, accI[ms][j], 40, wmma::mem_row_major);
        }
    __syncwarp();
    const int preP = m & 1;
    const int pimP = 2 + (m & 1);
    const int mrow = m >> 1;
    #pragma unroll 4
    for (int r = 0; r < 32; r++) {
        size_t gre = (((size_t)r * 4 + preP) * 256 + mrow) * Cc + warp * 32 + lane;
        size_t gim = (((size_t)r * 4 + pimP) * 256 + mrow) * Cc + warp * 32 + lane;
        g_G4[gre] = __float2half(bre[r * 40 + lane]);
        g_G4[gim] = __float2half(bim[r * 40 + lane]);
    }
}

// ---------------------------------------------------------------------------
// Inverse WMMA GEMM, persistent over batches, A (twiddles) smem-resident.
// (Unchanged from round 14.)
// ---------------------------------------------------------------------------
#define IA_BYTES 135168
#define IB_STAGE 34816

__global__ __launch_bounds__(512) void inv_gemm(const float* __restrict__ v,
                                                float* __restrict__ out) {
    extern __shared__ __align__(16) char sm[];
    const uint32_t sb = s2u(sm);
    const int tid = threadIdx.x;
    const int warp = tid >> 5;
    const int comp = warp >> 2;
    const int w4 = warp & 3;
    const int wm = w4 >> 1, wn = w4 & 1;
    const int colt = blockIdx.x, yt = blockIdx.y, bg = blockIdx.z;
    const int row0 = yt * 64, c0 = colt * 128;

    #pragma unroll
    for (int it = 0; it < 16; it++) {
        int idx = tid + 512 * it;
        int c = idx >> 11;
        int rem = idx & 2047;
        int r = rem >> 5, seg = rem & 31;
        size_t ga = ((size_t)c << 18) + (size_t)(row0 + r) * 256 + seg * 8;
        uint32_t ad = sb + c * 33792 + r * 528 + seg * 16;
        CP16(ad, g_Ai + ga);
    }
    CP_COMMIT();

    const __half* Asm = (const __half*)sm + comp * 16896;

    auto loadB = [&](int stage, int b, int k0) {
        uint32_t s0 = sb + IA_BYTES + stage * IB_STAGE;
        #pragma unroll
        for (int it = 0; it < 4; it++) {
            int idx = tid + 512 * it;
            int c = idx >> 9;
            int rem = idx & 511;
            int r = rem >> 4, seg = rem & 15;
            size_t gb = (((size_t)b * 4 + c) * 256 + k0 + r) * Cc + c0 + seg * 8;
            uint32_t bd = s0 + c * 8704 + r * 272 + seg * 16;
            CP16(bd, g_G4 + gb);
        }
        CP_COMMIT();
    };

    for (int bi = 0; bi < 8; bi++) {
        const int b = bg * 8 + bi;

        FragC acc[2][4];
        #pragma unroll
        for (int a = 0; a < 2; a++)
            #pragma unroll
            for (int j = 0; j < 4; j++) wmma::fill_fragment(acc[a][j], 0.0f);

        loadB(0, b, 0);
        loadB(1, b, 32);

        for (int c = 0; c < 8; c++) {
            if (c < 7) { CP_WAIT1(); } else { CP_WAIT0(); }
            __syncthreads();

            const int stg = c & 1;
            const __half* Bs = (const __half*)(sm + IA_BYTES + stg * IB_STAGE
                                               + comp * 8704);
            #pragma unroll
            for (int ks = 0; ks < 2; ks++) {
                const int kk = ks * 16;
                FragB bf[4];
                #pragma unroll
                for (int j = 0; j < 4; j++)
                    wmma::load_matrix_sync(bf[j], Bs + kk * 136 + wn * 64 + j * 16, 136);
                #pragma unroll
                for (int ms = 0; ms < 2; ms++) {
                    FragA af;
                    wmma::load_matrix_sync(af, Asm + (wm * 32 + ms * 16) * 264
                                               + c * 32 + kk, 264);
                    #pragma unroll
                    for (int j = 0; j < 4; j++)
                        wmma::mma_sync(acc[ms][j], af, bf[j], acc[ms][j]);
                }
            }
            __syncthreads();
            if (c + 2 < 8) loadB(stg, b, (c + 2) * 32);
        }

        float* bufs = (float*)(sm + IA_BYTES);
        float* buf = bufs + comp * 4352;
        const float* Ceb = bufs;
        const float* Cob = bufs + 4352;
        const float* Seb = bufs + 8704;
        const float* Sob = bufs + 13056;
        const size_t rowb = (size_t)b * Nn;

        #pragma unroll
        for (int h = 0; h < 2; h++) {
            if (wn == h) {
                #pragma unroll
                for (int ms = 0; ms < 2; ms++)
                    #pragma unroll
                    for (int j = 0; j < 4; j++)
                        wmma::store_matrix_sync(buf + (wm * 32 + ms * 16) * 68 + j * 16,
                                                acc[ms][j], 68, wmma::mem_row_major);
            }
            __syncthreads();

            #pragma unroll
            for (int it = 0; it < 2; it++) {
                int idx = tid + 512 * it;
                int r = idx >> 4, c4 = idx & 15;
                int off = r * 68 + c4 * 4;
                float4 Ce = *(const float4*)(Ceb + off);
                float4 Co = *(const float4*)(Cob + off);
                float4 Se = *(const float4*)(Seb + off);
                float4 So = *(const float4*)(Sob + off);
                float4 A1 = make_float4(Ce.x + Co.x, Ce.y + Co.y, Ce.z + Co.z, Ce.w + Co.w);
                float4 A2 = make_float4(Se.x + So.x, Se.y + So.y, Se.z + So.z, Se.w + So.w);
                float4 A3 = make_float4(Ce.x - Co.x, Ce.y - Co.y, Ce.z - Co.z, Ce.w - Co.w);
                float4 A4 = make_float4(Se.x - So.x, Se.y - So.y, Se.z - So.z, Se.w - So.w);
                int n = row0 + r;
                int o = c0 + h * 64 + c4 * 4;
                {
                    size_t i1 = (rowb + n) * Cc + o;
                    float4 vv = *(const float4*)(v + i1);
                    *(float4*)(out + i1) = make_float4(vv.x + A1.x - A2.x, vv.y + A1.y - A2.y,
                                                       vv.z + A1.z - A2.z, vv.w + A1.w - A2.w);
                }
                if (n > 0) {
                    size_t i2 = (rowb + (Nn - n)) * Cc + o;
                    float4 vv = *(const float4*)(v + i2);
                    *(float4*)(out + i2) = make_float4(vv.x + A1.x + A2.x, vv.y + A1.y + A2.y,
                                                       vv.z + A1.z + A2.z, vv.w + A1.w + A2.w);
                }
                {
                    size_t i3 = (rowb + (2048 - n)) * Cc + o;
                    float4 vv = *(const float4*)(v + i3);
                    *(float4*)(out + i3) = make_float4(vv.x + A3.x + A4.x, vv.y + A3.y + A4.y,
                                                       vv.z + A3.z + A4.z, vv.w + A3.w + A4.w);
                }
                if (n > 0) {
                    size_t i4 = (rowb + (2048 + n)) * Cc + o;
                    float4 vv = *(const float4*)(v + i4);
                    *(float4*)(out + i4) = make_float4(vv.x + A3.x - A4.x, vv.y + A3.y - A4.y,
                                                       vv.z + A3.z - A4.z, vv.w + A3.w - A4.w);
                }
            }
            __syncthreads();
        }
    }
}

// ---------------------------------------------------------------------------
// rowQ: n = 1024. out[1024] = v + C - S;  out[3072] = v + C + S.
// ---------------------------------------------------------------------------
__global__ __launch_bounds__(64) void rowQ(const float* __restrict__ v,
                                           float* __restrict__ out) {
    const int b = blockIdx.x;
    const int o = threadIdx.x * 4;
    float c0 = 0.f, c1 = 0.f, c2 = 0.f, c3 = 0.f;
    float s0 = 0.f, s1 = 0.f, s2 = 0.f, s3 = 0.f;
    const __half* GreE = g_G4 + ((size_t)b * 4 + 0) * 65536;
    const __half* GimO = g_G4 + ((size_t)b * 4 + 3) * 65536;
    #pragma unroll 8
    for (int mp = 0; mp < 256; mp++) {
        float sgn = (mp & 1) ? -1.0f : 1.0f;
        const __half* gr = GreE + (size_t)mp * Cc + o;
        const __half* gi = GimO + (size_t)mp * Cc + o;
        __half2 ra = *(const __half2*)(gr), rb = *(const __half2*)(gr + 2);
        __half2 ia = *(const __half2*)(gi), ib = *(const __half2*)(gi + 2);
        c0 += sgn * __half2float(ra.x); c1 += sgn * __half2float(ra.y);
        c2 += sgn * __half2float(rb.x); c3 += sgn * __half2float(rb.y);
        s0 += sgn * __half2float(ia.x); s1 += sgn * __half2float(ia.y);
        s2 += sgn * __half2float(ib.x); s3 += sgn * __half2float(ib.y);
    }
    size_t i1 = ((size_t)b * Nn + 1024) * Cc + o;
    size_t i2 = ((size_t)b * Nn + 3072) * Cc + o;
    float4 v1 = *(const float4*)(v + i1);
    float4 v2 = *(const float4*)(v + i2);
    *(float4*)(out + i1) = make_float4(v1.x + c0 - s0, v1.y + c1 - s1,
                                       v1.z + c2 - s2, v1.w + c3 - s3);
    *(float4*)(out + i2) = make_float4(v2.x + c0 + s0, v2.y + c1 + s1,
                                       v2.z + c2 + s2, v2.w + c3 + s3);
}

// ---------------------------------------------------------------------------
extern "C" void kernel_launch(void* const* d_in, const int* in_sizes, int n_in,
                              void* d_out, int out_size) {
    const float* v = (const float*)d_in[0];
    const float* R = (const float*)d_in[1];
    float* out = (float*)d_out;

    const int smF = 4 * STAGE;              // 108544
    const int smMid = 81920;                // epi bounce is the max region
    const int smInv = IA_BYTES + 69632;     // 204800
    cudaFuncSetAttribute(fwd_gemm, cudaFuncAttributeMaxDynamicSharedMemorySize, smF);
    cudaFuncSetAttribute(mid_wmma, cudaFuncAttributeMaxDynamicSharedMemorySize, smMid);
    cudaFuncSetAttribute(inv_gemm, cudaFuncAttributeMaxDynamicSharedMemorySize, smInv);

    prep_all<<<PREP_BLOCKS, 256>>>(v);
    fwd_gemm<<<dim3(1, 8, Bb), 512, smF>>>();
    mid_wmma<<<Mm, 256, smMid>>>(R);
    inv_gemm<<<dim3(2, 16, 4), 512, smInv>>>(v, out);
    rowQ<<<Bb, 64>>>(v, out);
}